// round 8
// baseline (speedup 1.0000x reference)
#include <cuda_runtime.h>
#include <cuda_bf16.h>
#include <math.h>
#include <stdint.h>

#define Bsz 16384
#define Hd  128
#define Cc  4
#define Ll  6
#define NHh 4
#define HDd 32
#define Oo  1024
#define G3H 384

// ---------------- fp32 scratch ----------------------------------------------
__device__ __align__(256) float g_qkv[(size_t)Cc * Bsz * G3H];
__device__ __align__(256) float g_hn [(size_t)Cc * Bsz * Hd];
__device__ __align__(256) float g_msg[(size_t)Cc * Bsz * Hd];

// ---------------- bf16 hi/lo split buffers ----------------------------------
__device__ __align__(256) __nv_bfloat16 g_x0h[(size_t)Bsz * Hd];
__device__ __align__(256) __nv_bfloat16 g_x0l[(size_t)Bsz * Hd];
__device__ __align__(256) __nv_bfloat16 g_hh [(size_t)Ll * Cc * Bsz * Hd];  // h_in split
__device__ __align__(256) __nv_bfloat16 g_hl [(size_t)Ll * Cc * Bsz * Hd];
__device__ __align__(256) __nv_bfloat16 g_nh [(size_t)Cc * Bsz * Hd];       // hn split
__device__ __align__(256) __nv_bfloat16 g_nl [(size_t)Cc * Bsz * Hd];
__device__ __align__(256) __nv_bfloat16 g_aah[(size_t)Cc * Bsz * Hd];       // att split
__device__ __align__(256) __nv_bfloat16 g_aal[(size_t)Cc * Bsz * Hd];
__device__ __align__(256) __nv_bfloat16 g_ph [(size_t)Cc * Bsz * Hd];       // hOut split
__device__ __align__(256) __nv_bfloat16 g_pl [(size_t)Cc * Bsz * Hd];
// weights (gate weights stored PERMUTED: row p = gate p%3, hidden p/3)
__device__ __align__(256) __nv_bfloat16 g_wih0h[(size_t)G3H * Hd];
__device__ __align__(256) __nv_bfloat16 g_wih0l[(size_t)G3H * Hd];
__device__ __align__(256) __nv_bfloat16 g_whh0h[(size_t)Cc * G3H * Hd];
__device__ __align__(256) __nv_bfloat16 g_whh0l[(size_t)Cc * G3H * Hd];
__device__ __align__(256) __nv_bfloat16 g_wihh[(size_t)(Ll-1) * Cc * G3H * Hd];
__device__ __align__(256) __nv_bfloat16 g_wihl[(size_t)(Ll-1) * Cc * G3H * Hd];
__device__ __align__(256) __nv_bfloat16 g_whhh[(size_t)(Ll-1) * Cc * G3H * Hd];
__device__ __align__(256) __nv_bfloat16 g_whhl[(size_t)(Ll-1) * Cc * G3H * Hd];
__device__ __align__(256) __nv_bfloat16 g_aiwh[(size_t)Ll * G3H * Hd];
__device__ __align__(256) __nv_bfloat16 g_aiwl[(size_t)Ll * G3H * Hd];
__device__ __align__(256) __nv_bfloat16 g_aowh[(size_t)Ll * Hd * Hd];
__device__ __align__(256) __nv_bfloat16 g_aowl[(size_t)Ll * Hd * Hd];
__device__ __align__(256) __nv_bfloat16 g_hwh [(size_t)Oo * Hd];
__device__ __align__(256) __nv_bfloat16 g_hwl [(size_t)Oo * Hd];
// permuted fp32 gate biases
__device__ __align__(256) float g_bih0P[(size_t)Cc * G3H];
__device__ __align__(256) float g_bhh0P[(size_t)Cc * G3H];
__device__ __align__(256) float g_bihP [(size_t)(Ll-1) * Cc * G3H];
__device__ __align__(256) float g_bhhP [(size_t)(Ll-1) * Cc * G3H];

__device__ __forceinline__ float sigf(float x) { return 1.0f / (1.0f + expf(-x)); }

__device__ __forceinline__ uint32_t pack_bf16(__nv_bfloat16 a, __nv_bfloat16 b) {
    __nv_bfloat162 t = __nv_bfloat162(a, b);
    return *reinterpret_cast<uint32_t*>(&t);
}

__device__ __forceinline__ void store_split4(__nv_bfloat16* ph, __nv_bfloat16* pl,
                                             long off, float4 v) {
    __nv_bfloat16 h0 = __float2bfloat16(v.x);
    __nv_bfloat16 h1 = __float2bfloat16(v.y);
    __nv_bfloat16 h2 = __float2bfloat16(v.z);
    __nv_bfloat16 h3 = __float2bfloat16(v.w);
    *reinterpret_cast<uint2*>(ph + off) =
        make_uint2(pack_bf16(h0, h1), pack_bf16(h2, h3));
    __nv_bfloat16 l0 = __float2bfloat16(v.x - __bfloat162float(h0));
    __nv_bfloat16 l1 = __float2bfloat16(v.y - __bfloat162float(h1));
    __nv_bfloat16 l2 = __float2bfloat16(v.z - __bfloat162float(h2));
    __nv_bfloat16 l3 = __float2bfloat16(v.w - __bfloat162float(h3));
    *reinterpret_cast<uint2*>(pl + off) =
        make_uint2(pack_bf16(l0, l1), pack_bf16(l2, l3));
}

// ---------------- generic fp32 -> bf16 hi/lo split pass ---------------------
__global__ void split_pair(const float* __restrict__ in, __nv_bfloat16* __restrict__ oh,
                           __nv_bfloat16* __restrict__ ol)
{
    long i = (long)blockIdx.x * 256 + threadIdx.x;   // float4 index
    float4 v = reinterpret_cast<const float4*>(in)[i];
    store_split4(oh, ol, i * 4, v);
}

// ---------------- gate weight permute + split --------------------------------
// in: [M][384][128] fp32; out row p = in row (p%3)*128 + p/3  (within matrix)
__global__ void permute_split_w(const float* __restrict__ in,
                                __nv_bfloat16* __restrict__ oh,
                                __nv_bfloat16* __restrict__ ol)
{
    long i = (long)blockIdx.x * 256 + threadIdx.x;   // float4 units
    int  k4 = (int)(i & 31);
    long row = i >> 5;                               // m*384 + p
    int  p = (int)(row % 384);
    long m = row / 384;
    long src = (m * 384 + (long)(p % 3) * 128 + p / 3) * 128 + k4 * 4;
    float4 v = *(const float4*)(in + src);
    store_split4(oh, ol, row * 128 + (long)k4 * 4, v);
}

__global__ void permute_bias(const float* __restrict__ in, float* __restrict__ out, int total)
{
    int i = blockIdx.x * 256 + threadIdx.x;
    if (i >= total) return;
    int p = i % 384;
    int m = i / 384;
    out[i] = in[m * 384 + (p % 3) * 128 + p / 3];
}

// ======================= shared GEMM machinery =======================
#define KPAD    136
#define ROWB    (KPAD * 2)            // 272 bytes per row (LDSM conflict-free)

__device__ __forceinline__ uint32_t smem_u32(const void* p) {
    uint32_t a;
    asm("{ .reg .u64 t; cvta.to.shared.u64 t, %1; cvt.u32.u64 %0, t; }" : "=r"(a) : "l"(p));
    return a;
}
__device__ __forceinline__ void cpa16(uint32_t sdst, const void* gsrc) {
    asm volatile("cp.async.cg.shared.global [%0], [%1], 16;" :: "r"(sdst), "l"(gsrc));
}
#define CP_COMMIT() asm volatile("cp.async.commit_group;" ::: "memory")
#define CP_WAIT(n)  asm volatile("cp.async.wait_group %0;" :: "n"(n) : "memory")

__device__ __forceinline__ void mma16816(float* c, const uint32_t* a, const uint32_t* b) {
    asm volatile(
        "mma.sync.aligned.m16n8k16.row.col.f32.bf16.bf16.f32 "
        "{%0,%1,%2,%3}, {%4,%5,%6,%7}, {%8,%9}, {%0,%1,%2,%3};\n"
        : "+f"(c[0]), "+f"(c[1]), "+f"(c[2]), "+f"(c[3])
        : "r"(a[0]), "r"(a[1]), "r"(a[2]), "r"(a[3]), "r"(b[0]), "r"(b[1]));
}

#define LDSM_X4(r0, r1, r2, r3, addr) \
    asm volatile("ldmatrix.sync.aligned.m8n8.x4.shared.b16 {%0,%1,%2,%3}, [%4];" \
                 : "=r"(r0), "=r"(r1), "=r"(r2), "=r"(r3) : "r"(addr))

// ======================= plain GEMM (R6 config: 256 thr, warp 32x32) =========
#define TILE_A  ((size_t)128 * ROWB)
#define TILE_Bt ((size_t)64  * ROWB)
#define SM_AH   0
#define SM_AL   (SM_AH + TILE_A)
#define SM_BH   (SM_AL + TILE_A)
#define SM_BL   (SM_BH + TILE_Bt)
#define SM_TOT  (SM_BL + TILE_Bt)     // 104448

struct Frags {
    uint32_t ah[2][4];
    uint32_t al[2][4];
    uint32_t bh[4][2];
    uint32_t bl[4][2];
};

__device__ __forceinline__ void ld_frags(Frags& f, uint32_t aH, uint32_t aL,
                                         uint32_t bH, uint32_t bL) {
    #pragma unroll
    for (int i = 0; i < 2; i++)
        LDSM_X4(f.ah[i][0], f.ah[i][1], f.ah[i][2], f.ah[i][3], aH + i * (16 * ROWB));
    #pragma unroll
    for (int i = 0; i < 2; i++)
        LDSM_X4(f.al[i][0], f.al[i][1], f.al[i][2], f.al[i][3], aL + i * (16 * ROWB));
    LDSM_X4(f.bh[0][0], f.bh[0][1], f.bh[1][0], f.bh[1][1], bH);
    LDSM_X4(f.bh[2][0], f.bh[2][1], f.bh[3][0], f.bh[3][1], bH + 16 * ROWB);
    LDSM_X4(f.bl[0][0], f.bl[0][1], f.bl[1][0], f.bl[1][1], bL);
    LDSM_X4(f.bl[2][0], f.bl[2][1], f.bl[3][0], f.bl[3][1], bL + 16 * ROWB);
}

__global__ __launch_bounds__(256, 2) void gemm_tc(
    const __nv_bfloat16* __restrict__ Ah, const __nv_bfloat16* __restrict__ Al,
    const __nv_bfloat16* __restrict__ Bh, const __nv_bfloat16* __restrict__ Bl,
    const float* __restrict__ bias, float* __restrict__ Y,
    int G, long xStride, long wStride, long bStride, long yStride)
{
    extern __shared__ char smem[];

    int c = blockIdx.z;
    Ah   += (long)c * xStride;
    Al   += (long)c * xStride;
    Bh   += (long)c * wStride;
    Bl   += (long)c * wStride;
    bias += (long)c * bStride;
    Y    += (long)c * yStride;

    int b0   = blockIdx.x * 128;
    int g0   = blockIdx.y * 64;
    int tid  = threadIdx.x;
    int wid  = tid >> 5;
    int lane = tid & 31;

    const __nv_bfloat16* a_h = Ah + (long)b0 * 128;
    const __nv_bfloat16* a_l = Al + (long)b0 * 128;
    const __nv_bfloat16* b_h = Bh + (long)g0 * 128;
    const __nv_bfloat16* b_l = Bl + (long)g0 * 128;

    uint32_t sb = smem_u32(smem);

    #pragma unroll 2
    for (int idx = tid; idx < 2048; idx += 256) {
        int r = idx >> 4, k = idx & 15;
        cpa16(sb + SM_AH + r * ROWB + k * 16, a_h + (long)r * 128 + k * 8);
        cpa16(sb + SM_AL + r * ROWB + k * 16, a_l + (long)r * 128 + k * 8);
    }
    #pragma unroll 2
    for (int idx = tid; idx < 1024; idx += 256) {
        int r = idx >> 4, k = idx & 15;
        cpa16(sb + SM_BH + r * ROWB + k * 16, b_h + (long)r * 128 + k * 8);
        cpa16(sb + SM_BL + r * ROWB + k * 16, b_l + (long)r * 128 + k * 8);
    }
    CP_COMMIT();
    CP_WAIT(0);
    __syncthreads();

    int wm = (wid & 3) * 32;
    int wn = (wid >> 2) * 32;

    int a_lane = (wm + (lane & 7) + ((lane >> 3) & 1) * 8) * ROWB + (lane >> 4) * 16;
    int b_lane = (wn + (lane & 7) + ((lane >> 4) & 1) * 8) * ROWB + ((lane >> 3) & 1) * 16;

    uint32_t aH = sb + SM_AH + a_lane;
    uint32_t aL = sb + SM_AL + a_lane;
    uint32_t bH = sb + SM_BH + b_lane;
    uint32_t bL = sb + SM_BL + b_lane;

    float acc[2][4][4];
    #pragma unroll
    for (int i = 0; i < 2; i++)
        #pragma unroll
        for (int j = 0; j < 4; j++)
            #pragma unroll
            for (int r = 0; r < 4; r++) acc[i][j][r] = 0.0f;

    Frags fr[2];
    ld_frags(fr[0], aH, aL, bH, bL);

    #pragma unroll
    for (int kk = 0; kk < 8; kk++) {
        if (kk < 7) {
            int ko = (kk + 1) * 32;
            ld_frags(fr[(kk + 1) & 1], aH + ko, aL + ko, bH + ko, bL + ko);
        }
        Frags& f = fr[kk & 1];
        #pragma unroll
        for (int i = 0; i < 2; i++)
            #pragma unroll
            for (int j = 0; j < 4; j++) {
                mma16816(acc[i][j], f.ah[i], f.bh[j]);
                mma16816(acc[i][j], f.ah[i], f.bl[j]);
                mma16816(acc[i][j], f.al[i], f.bh[j]);
            }
    }

    int colb = g0 + wn + (lane & 3) * 2;
    #pragma unroll
    for (int i = 0; i < 2; i++) {
        int row = b0 + wm + i * 16 + (lane >> 2);
        #pragma unroll
        for (int j = 0; j < 4; j++) {
            int col = colb + j * 8;
            float bx = bias[col], by = bias[col + 1];
            float2 o0 = make_float2(acc[i][j][0] + bx, acc[i][j][1] + by);
            float2 o1 = make_float2(acc[i][j][2] + bx, acc[i][j][3] + by);
            *reinterpret_cast<float2*>(Y + (long)row * G + col)       = o0;
            *reinterpret_cast<float2*>(Y + (long)(row + 8) * G + col) = o1;
        }
    }
}

// ======================= fused gi-GEMM + gh-GEMM + GRU =======================
// CTA: 128(b) x 96(g') tile (32 hidden units), 256 threads, 8 warps (4m x 2n),
// warp tile 32 x 48. Two GEMM passes staged to smem, then GRU epilogue.
#define F_AG_H   0
#define F_AG_L   34816
#define F_AH_H   69632
#define F_AH_L   104448
#define F_W_H    139264
#define F_W_L    165376
#define F_TOT    191488
#define STG1     F_AG_H       // fp32 gi stage, stride 98 floats (50176 B <= 69632)
#define STG2     F_W_H        // fp32 gh stage (50176 B <= 52224)

struct PFrag {
    uint32_t ah[2][4], al[2][4];
    uint32_t bh[6][2], bl[6][2];
};

__device__ __forceinline__ void p_ld(PFrag& f, uint32_t aH, uint32_t aL,
                                     uint32_t bH, uint32_t bL) {
    #pragma unroll
    for (int i = 0; i < 2; i++) {
        LDSM_X4(f.ah[i][0], f.ah[i][1], f.ah[i][2], f.ah[i][3], aH + i * (16 * ROWB));
        LDSM_X4(f.al[i][0], f.al[i][1], f.al[i][2], f.al[i][3], aL + i * (16 * ROWB));
    }
    #pragma unroll
    for (int j = 0; j < 3; j++) {
        LDSM_X4(f.bh[2*j][0], f.bh[2*j][1], f.bh[2*j+1][0], f.bh[2*j+1][1],
                bH + j * (16 * ROWB));
        LDSM_X4(f.bl[2*j][0], f.bl[2*j][1], f.bl[2*j+1][0], f.bl[2*j+1][1],
                bL + j * (16 * ROWB));
    }
}

// one 128x96 GEMM pass; result staged as fp32 (stride 98) at stgOff.
// Internal __syncthreads between mainloop and staging (callers keep it CTA-uniform).
__device__ __forceinline__ void gemm_pass(char* smem, uint32_t sb,
        int aOffH, int aOffL, int wOffH, int wOffL, int stgOff,
        int a_lane, int b_lane, int wm, int wn, int lane)
{
    uint32_t aH = sb + aOffH + a_lane, aL = sb + aOffL + a_lane;
    uint32_t bH = sb + wOffH + b_lane, bL = sb + wOffL + b_lane;

    float acc[2][6][4];
    #pragma unroll
    for (int i = 0; i < 2; i++)
        #pragma unroll
        for (int j = 0; j < 6; j++)
            #pragma unroll
            for (int r = 0; r < 4; r++) acc[i][j][r] = 0.0f;

    PFrag fr[2];
    p_ld(fr[0], aH, aL, bH, bL);

    #pragma unroll
    for (int kk = 0; kk < 8; kk++) {
        if (kk < 7) {
            int ko = (kk + 1) * 32;
            p_ld(fr[(kk + 1) & 1], aH + ko, aL + ko, bH + ko, bL + ko);
        }
        PFrag& f = fr[kk & 1];
        #pragma unroll
        for (int i = 0; i < 2; i++)
            #pragma unroll
            for (int j = 0; j < 6; j++) {
                mma16816(acc[i][j], f.ah[i], f.bh[j]);
                mma16816(acc[i][j], f.ah[i], f.bl[j]);
                mma16816(acc[i][j], f.al[i], f.bh[j]);
            }
    }

    __syncthreads();   // all warps done reading the operand tiles
    float* stg = reinterpret_cast<float*>(smem + stgOff);
    #pragma unroll
    for (int i = 0; i < 2; i++) {
        int row = wm + i * 16 + (lane >> 2);
        #pragma unroll
        for (int j = 0; j < 6; j++) {
            int col = wn + (lane & 3) * 2 + j * 8;
            *reinterpret_cast<float2*>(&stg[row * 98 + col]) =
                make_float2(acc[i][j][0], acc[i][j][1]);
            *reinterpret_cast<float2*>(&stg[(row + 8) * 98 + col]) =
                make_float2(acc[i][j][2], acc[i][j][3]);
        }
    }
}

__global__ __launch_bounds__(256, 1) void gigh_gru(
    const __nv_bfloat16* __restrict__ giAh, const __nv_bfloat16* __restrict__ giAl,
    long giStride,
    const __nv_bfloat16* __restrict__ wiH,  const __nv_bfloat16* __restrict__ wiL,
    long wiStride,
    const float* __restrict__ biP,
    const __nv_bfloat16* __restrict__ hhH,  const __nv_bfloat16* __restrict__ hhL,
    const __nv_bfloat16* __restrict__ whH,  const __nv_bfloat16* __restrict__ whL,
    const float* __restrict__ bhP,
    const float* __restrict__ hprev,
    float* __restrict__ hnOut,
    __nv_bfloat16* __restrict__ nhOut, __nv_bfloat16* __restrict__ nlOut,
    int l0flag)
{
    extern __shared__ char smem[];
    uint32_t sb = smem_u32(smem);

    int b0 = blockIdx.x * 128;
    int g0 = blockIdx.y * 96;
    int h0 = blockIdx.y * 32;
    int c  = blockIdx.z;
    int tid = threadIdx.x, wid = tid >> 5, lane = tid & 31;
    bool skipGi = (l0flag != 0) && (c > 0);

    const __nv_bfloat16* agh = giAh + (long)c * giStride + (long)b0 * 128;
    const __nv_bfloat16* agl = giAl + (long)c * giStride + (long)b0 * 128;
    const __nv_bfloat16* wih = wiH + (long)c * wiStride + (long)g0 * 128;
    const __nv_bfloat16* wil = wiL + (long)c * wiStride + (long)g0 * 128;
    const __nv_bfloat16* ahh = hhH + ((long)c * Bsz + b0) * 128;
    const __nv_bfloat16* ahl = hhL + ((long)c * Bsz + b0) * 128;
    const __nv_bfloat16* whh_ = whH + (long)c * ((long)G3H * Hd) + (long)g0 * 128;
    const __nv_bfloat16* whl_ = whL + (long)c * ((long)G3H * Hd) + (long)g0 * 128;

    // group0: A_gi + W_ih
    if (!skipGi) {
        #pragma unroll 2
        for (int idx = tid; idx < 2048; idx += 256) {
            int r = idx >> 4, k = idx & 15;
            cpa16(sb + F_AG_H + r * ROWB + k * 16, agh + (long)r * 128 + k * 8);
            cpa16(sb + F_AG_L + r * ROWB + k * 16, agl + (long)r * 128 + k * 8);
        }
        #pragma unroll 2
        for (int idx = tid; idx < 1536; idx += 256) {
            int r = idx >> 4, k = idx & 15;
            cpa16(sb + F_W_H + r * ROWB + k * 16, wih + (long)r * 128 + k * 8);
            cpa16(sb + F_W_L + r * ROWB + k * 16, wil + (long)r * 128 + k * 8);
        }
    }
    CP_COMMIT();
    // group1: A_hh
    #pragma unroll 2
    for (int idx = tid; idx < 2048; idx += 256) {
        int r = idx >> 4, k = idx & 15;
        cpa16(sb + F_AH_H + r * ROWB + k * 16, ahh + (long)r * 128 + k * 8);
        cpa16(sb + F_AH_L + r * ROWB + k * 16, ahl + (long)r * 128 + k * 8);
    }
    CP_COMMIT();

    int wm = (wid & 3) * 32;
    int wn = (wid >> 2) * 48;
    int a_lane = (wm + (lane & 7) + ((lane >> 3) & 1) * 8) * ROWB + (lane >> 4) * 16;
    int b_lane = (wn + (lane & 7) + ((lane >> 4) & 1) * 8) * ROWB + ((lane >> 3) & 1) * 16;

    if (!skipGi) {
        CP_WAIT(1);
        __syncthreads();
        gemm_pass(smem, sb, F_AG_H, F_AG_L, F_W_H, F_W_L, STG1,
                  a_lane, b_lane, wm, wn, lane);
        // pass1's internal sync guarantees W_ih reads complete before refill below
    }

    // group2: W_hh into the (now free) W slot
    #pragma unroll 2
    for (int idx = tid; idx < 1536; idx += 256) {
        int r = idx >> 4, k = idx & 15;
        cpa16(sb + F_W_H + r * ROWB + k * 16, whh_ + (long)r * 128 + k * 8);
        cpa16(sb + F_W_L + r * ROWB + k * 16, whl_ + (long)r * 128 + k * 8);
    }
    CP_COMMIT();
    CP_WAIT(0);
    __syncthreads();

    gemm_pass(smem, sb, F_AH_H, F_AH_L, F_W_H, F_W_L, STG2,
              a_lane, b_lane, wm, wn, lane);
    __syncthreads();   // stage2 visible to all

    // ---- GRU epilogue: 128 rows x 32 hidden units ----
    const float* st1 = reinterpret_cast<const float*>(smem + STG1);
    const float* st2 = reinterpret_cast<const float*>(smem + STG2);
    #pragma unroll
    for (int it = 0; it < 16; it++) {
        int u = tid + it * 256;
        int r = u >> 5;
        int h = lane;
        int col = 3 * h;
        float gir = 0.f, giz = 0.f, gin = 0.f;
        if (!skipGi) {
            gir = st1[r * 98 + col];
            giz = st1[r * 98 + col + 1];
            gin = st1[r * 98 + col + 2];
        }
        float ghr = st2[r * 98 + col];
        float ghz = st2[r * 98 + col + 1];
        float ghn = st2[r * 98 + col + 2];

        long bb = (long)c * G3H + g0 + col;
        float irv = gir + biP[bb];
        float izv = giz + biP[bb + 1];
        float inv = gin + biP[bb + 2];
        float hrv = ghr + bhP[bb];
        float hzv = ghz + bhP[bb + 1];
        float hnv = ghn + bhP[bb + 2];

        float rr = sigf(irv + hrv);
        float zz = sigf(izv + hzv);
        float nn = tanhf(inv + rr * hnv);

        long go = ((long)c * Bsz + b0 + r) * 128 + h0 + h;
        float hp = hprev[go];
        float out = (1.0f - zz) * nn + zz * hp;
        hnOut[go] = out;
        __nv_bfloat16 oh = __float2bfloat16(out);
        nhOut[go] = oh;
        nlOut[go] = __float2bfloat16(out - __bfloat162float(oh));
    }
}

// ---------------- embedding gather -> bf16 hi/lo split -----------------------
__global__ void gather_x0(const int* __restrict__ tok, const float* __restrict__ emb)
{
    long t = (long)blockIdx.x * 256 + threadIdx.x;   // B*32 threads
    int b  = (int)(t >> 5);
    int e4 = (int)(t & 31) << 2;
    float4 v = *(const float4*)(emb + (long)tok[b] * 128 + e4);
    store_split4(g_x0h, g_x0l, (long)b * 128 + e4, v);
}

// ---------------- tiny attention over C=4 positions -> bf16 split ------------
__global__ void attn_kernel()
{
    int gw   = blockIdx.x * 4 + (threadIdx.x >> 5);
    int lane = threadIdx.x & 31;
    int b  = gw >> 2;
    int nh = gw & 3;

    float q[4], k[4], v[4];
    #pragma unroll
    for (int c = 0; c < 4; c++) {
        const float* p = g_qkv + ((long)c * Bsz + b) * G3H + nh * 32 + lane;
        q[c] = p[0];
        k[c] = p[128];
        v[c] = p[256];
    }

    float s[4][4];
    #pragma unroll
    for (int qc = 0; qc < 4; qc++) {
        #pragma unroll
        for (int kc = 0; kc < 4; kc++) {
            float p = q[qc] * k[kc];
            #pragma unroll
            for (int off = 16; off > 0; off >>= 1)
                p += __shfl_xor_sync(0xFFFFFFFFu, p, off);
            s[qc][kc] = p * 0.17677669529663687f;   // 1/sqrt(32)
        }
    }

    #pragma unroll
    for (int qc = 0; qc < 4; qc++) {
        float m = fmaxf(fmaxf(s[qc][0], s[qc][1]), fmaxf(s[qc][2], s[qc][3]));
        float e0 = expf(s[qc][0] - m), e1 = expf(s[qc][1] - m);
        float e2 = expf(s[qc][2] - m), e3 = expf(s[qc][3] - m);
        float inv = 1.0f / (e0 + e1 + e2 + e3);
        float o = (e0 * v[0] + e1 * v[1] + e2 * v[2] + e3 * v[3]) * inv;
        long off = ((long)qc * Bsz + b) * 128 + nh * 32 + lane;
        __nv_bfloat16 h = __float2bfloat16(o);
        g_aah[off] = h;
        g_aal[off] = __float2bfloat16(o - __bfloat162float(h));
    }
}

// ---------------- fused LayerNorm + gate + blend -----------------------------
__global__ void lngate_kernel(const float* __restrict__ gg, const float* __restrict__ bb,
                              const float* __restrict__ gw, const float* __restrict__ gbp,
                              float* __restrict__ hout)
{
    int row  = blockIdx.x * 4 + (threadIdx.x >> 5);
    int lane = threadIdx.x & 31;
    const float* mp = g_msg + (long)row * 128;
    const float* hp = g_hn  + (long)row * 128;

    float4 x = *(const float4*)(mp + lane * 4);
    float s = x.x + x.y + x.z + x.w;
    #pragma unroll
    for (int off = 16; off > 0; off >>= 1) s += __shfl_xor_sync(0xFFFFFFFFu, s, off);
    float mean = s * (1.0f / 128.0f);

    float dx = x.x - mean, dy = x.y - mean, dz = x.z - mean, dw = x.w - mean;
    float sq = dx * dx + dy * dy + dz * dz + dw * dw;
    #pragma unroll
    for (int off = 16; off > 0; off >>= 1) sq += __shfl_xor_sync(0xFFFFFFFFu, sq, off);
    float rstd = rsqrtf(sq * (1.0f / 128.0f) + 1e-5f);

    float4 gv = *(const float4*)(gg + lane * 4);
    float4 bv = *(const float4*)(bb + lane * 4);
    float4 m;
    m.x = dx * rstd * gv.x + bv.x;
    m.y = dy * rstd * gv.y + bv.y;
    m.z = dz * rstd * gv.z + bv.z;
    m.w = dw * rstd * gv.w + bv.w;

    float4 hv = *(const float4*)(hp + lane * 4);
    float4 w1 = *(const float4*)(gw + lane * 4);
    float4 w2 = *(const float4*)(gw + 128 + lane * 4);

    float p = hv.x * w1.x + hv.y * w1.y + hv.z * w1.z + hv.w * w1.w
            + m.x * w2.x + m.y * w2.y + m.z * w2.z + m.w * w2.w;
    #pragma unroll
    for (int off = 16; off > 0; off >>= 1) p += __shfl_xor_sync(0xFFFFFFFFu, p, off);
    float gt = sigf(p + gbp[0]);

    float4 o;
    o.x = (1.0f - gt) * hv.x + gt * m.x;
    o.y = (1.0f - gt) * hv.y + gt * m.y;
    o.z = (1.0f - gt) * hv.z + gt * m.z;
    o.w = (1.0f - gt) * hv.w + gt * m.w;
    long off = (long)row * 128 + lane * 4;
    *(float4*)(hout + off) = o;
    store_split4(g_ph, g_pl, off, o);
}

// ---------------- host orchestration ----------------------------------------
extern "C" void kernel_launch(void* const* d_in, const int* in_sizes, int n_in,
                              void* d_out, int out_size)
{
    const int*   tokens     = (const int*)  d_in[0];
    const float* h_in       = (const float*)d_in[1];
    const float* emb        = (const float*)d_in[2];
    const float* wih0_c0    = (const float*)d_in[3];
    const float* bih0       = (const float*)d_in[5];
    const float* whh0       = (const float*)d_in[6];
    const float* bhh0       = (const float*)d_in[7];
    const float* wih        = (const float*)d_in[8];
    const float* whh        = (const float*)d_in[9];
    const float* bih        = (const float*)d_in[10];
    const float* bhh        = (const float*)d_in[11];
    const float* attn_in_w  = (const float*)d_in[12];
    const float* attn_in_b  = (const float*)d_in[13];
    const float* attn_out_w = (const float*)d_in[14];
    const float* attn_out_b = (const float*)d_in[15];
    const float* ln_g       = (const float*)d_in[16];
    const float* ln_b       = (const float*)d_in[17];
    const float* gate_w     = (const float*)d_in[18];
    const float* gate_b     = (const float*)d_in[19];
    const float* head_w     = (const float*)d_in[20];
    const float* head_b     = (const float*)d_in[21];

    float* yOut = (float*)d_out;                       // (B, O)
    float* hOut = yOut + (size_t)Bsz * Oo;             // (L, C, B, H)

    float *pqkv, *phn, *pmsg;
    cudaGetSymbolAddress((void**)&pqkv, g_qkv);
    cudaGetSymbolAddress((void**)&phn,  g_hn);
    cudaGetSymbolAddress((void**)&pmsg, g_msg);

    __nv_bfloat16 *x0h, *x0l, *hh, *hl, *nh, *nl, *aah, *aal, *ph, *pl;
    __nv_bfloat16 *wih0h, *wih0l, *whh0h, *whh0l, *wihh, *wihl, *whhh, *whhl;
    __nv_bfloat16 *aiwh, *aiwl, *aowh, *aowl, *hwh, *hwl;
    float *bih0P, *bhh0P, *bihP, *bhhP;
    cudaGetSymbolAddress((void**)&x0h, g_x0h);   cudaGetSymbolAddress((void**)&x0l, g_x0l);
    cudaGetSymbolAddress((void**)&hh,  g_hh);    cudaGetSymbolAddress((void**)&hl,  g_hl);
    cudaGetSymbolAddress((void**)&nh,  g_nh);    cudaGetSymbolAddress((void**)&nl,  g_nl);
    cudaGetSymbolAddress((void**)&aah, g_aah);   cudaGetSymbolAddress((void**)&aal, g_aal);
    cudaGetSymbolAddress((void**)&ph,  g_ph);    cudaGetSymbolAddress((void**)&pl,  g_pl);
    cudaGetSymbolAddress((void**)&wih0h, g_wih0h); cudaGetSymbolAddress((void**)&wih0l, g_wih0l);
    cudaGetSymbolAddress((void**)&whh0h, g_whh0h); cudaGetSymbolAddress((void**)&whh0l, g_whh0l);
    cudaGetSymbolAddress((void**)&wihh, g_wihh); cudaGetSymbolAddress((void**)&wihl, g_wihl);
    cudaGetSymbolAddress((void**)&whhh, g_whhh); cudaGetSymbolAddress((void**)&whhl, g_whhl);
    cudaGetSymbolAddress((void**)&aiwh, g_aiwh); cudaGetSymbolAddress((void**)&aiwl, g_aiwl);
    cudaGetSymbolAddress((void**)&aowh, g_aowh); cudaGetSymbolAddress((void**)&aowl, g_aowl);
    cudaGetSymbolAddress((void**)&hwh,  g_hwh);  cudaGetSymbolAddress((void**)&hwl,  g_hwl);
    cudaGetSymbolAddress((void**)&bih0P, g_bih0P); cudaGetSymbolAddress((void**)&bhh0P, g_bhh0P);
    cudaGetSymbolAddress((void**)&bihP,  g_bihP);  cudaGetSymbolAddress((void**)&bhhP,  g_bhhP);

    cudaFuncSetAttribute(gemm_tc,  cudaFuncAttributeMaxDynamicSharedMemorySize, SM_TOT);
    cudaFuncSetAttribute(gigh_gru, cudaFuncAttributeMaxDynamicSharedMemorySize, F_TOT);

    const long CBH = (long)Cc * Bsz * Hd;
    (void)in_sizes; (void)n_in; (void)out_size;

    // ---- prolog ----
    // gate weights: permute + split
    permute_split_w<<<(int)(((long)G3H * Hd / 4) / 256), 256>>>(wih0_c0, wih0h, wih0l);
    permute_split_w<<<(int)(((long)Cc * G3H * Hd / 4) / 256), 256>>>(whh0, whh0h, whh0l);
    permute_split_w<<<(int)(((long)(Ll-1) * Cc * G3H * Hd / 4) / 256), 256>>>(wih, wihh, wihl);
    permute_split_w<<<(int)(((long)(Ll-1) * Cc * G3H * Hd / 4) / 256), 256>>>(whh, whhh, whhl);
    // gate biases: permute (fp32)
    permute_bias<<<(Cc * G3H + 255) / 256, 256>>>(bih0, bih0P, Cc * G3H);
    permute_bias<<<(Cc * G3H + 255) / 256, 256>>>(bhh0, bhh0P, Cc * G3H);
    permute_bias<<<((Ll-1) * Cc * G3H + 255) / 256, 256>>>(bih, bihP, (Ll-1) * Cc * G3H);
    permute_bias<<<((Ll-1) * Cc * G3H + 255) / 256, 256>>>(bhh, bhhP, (Ll-1) * Cc * G3H);
    // plain splits
    split_pair<<<(int)(((long)Ll * G3H * Hd / 4) / 256), 256>>>(attn_in_w, aiwh, aiwl);
    split_pair<<<(int)(((long)Ll * Hd * Hd / 4) / 256), 256>>>(attn_out_w, aowh, aowl);
    split_pair<<<(int)(((long)Oo * Hd / 4) / 256), 256>>>(head_w, hwh, hwl);
    split_pair<<<(int)(((long)Ll * CBH / 4) / 256), 256>>>(h_in, hh, hl);
    gather_x0<<<(Bsz * 32) / 256, 256>>>(tokens, emb);

    dim3 gB(Bsz / 128, G3H / 64, Cc);
    dim3 gO(Bsz / 128, Hd  / 64, Cc);
    dim3 gF(Bsz / 128, 4, Cc);

    for (int l = 0; l < Ll; l++) {
        // ---- fused gi + gh + GRU ----
        const __nv_bfloat16 *giAh, *giAl, *wiH_, *wiL_, *whH_, *whL_;
        const float *biP_, *bhP_;
        long giStride, wiStride;
        if (l == 0) {
            giAh = x0h; giAl = x0l; giStride = 0;
            wiH_ = wih0h; wiL_ = wih0l; wiStride = 0;
            biP_ = bih0P; whH_ = whh0h; whL_ = whh0l; bhP_ = bhh0P;
        } else {
            giAh = ph; giAl = pl; giStride = (long)Bsz * Hd;
            wiH_ = wihh + (size_t)(l - 1) * Cc * G3H * Hd;
            wiL_ = wihl + (size_t)(l - 1) * Cc * G3H * Hd;
            wiStride = (long)G3H * Hd;
            biP_ = bihP + (size_t)(l - 1) * Cc * G3H;
            whH_ = whhh + (size_t)(l - 1) * Cc * G3H * Hd;
            whL_ = whhl + (size_t)(l - 1) * Cc * G3H * Hd;
            bhP_ = bhhP + (size_t)(l - 1) * Cc * G3H;
        }
        gigh_gru<<<gF, 256, F_TOT>>>(giAh, giAl, giStride, wiH_, wiL_, wiStride, biP_,
                                     hh + (size_t)l * CBH, hl + (size_t)l * CBH,
                                     whH_, whL_, bhP_,
                                     h_in + (size_t)l * CBH,
                                     phn, nh, nl, l == 0 ? 1 : 0);

        // ---- QKV ----
        gemm_tc<<<gB, 256, SM_TOT>>>(nh, nl,
                                     aiwh + (size_t)l * G3H * Hd,
                                     aiwl + (size_t)l * G3H * Hd,
                                     attn_in_b + (size_t)l * G3H,
                                     pqkv, G3H,
                                     (long)Bsz * Hd, 0, 0, (long)Bsz * G3H);

        // ---- attention ----
        attn_kernel<<<(Bsz * NHh) / 4, 128>>>();

        // ---- out projection ----
        gemm_tc<<<gO, 256, SM_TOT>>>(aah, aal,
                                     aowh + (size_t)l * Hd * Hd,
                                     aowl + (size_t)l * Hd * Hd,
                                     attn_out_b + (size_t)l * Hd,
                                     pmsg, Hd,
                                     (long)Bsz * Hd, 0, 0, (long)Bsz * Hd);

        // ---- fused LN + gate + blend -> hOut + g_ph/g_pl split ----
        lngate_kernel<<<(Cc * Bsz) / 4, 128>>>(ln_g + (size_t)l * Hd, ln_b + (size_t)l * Hd,
                                               gate_w + (size_t)l * 2 * Hd, gate_b + l,
                                               hOut + (size_t)l * CBH);
    }

    // ---- head: y = h_n[L-1, 0] @ head_w.T + head_b (cell 0 = g_ph offset 0) ----
    dim3 gH(Bsz / 128, Oo / 64, 1);
    gemm_tc<<<gH, 256, SM_TOT>>>(ph, pl, hwh, hwl, head_b, yOut, Oo, 0, 0, 0, 0);
}

// round 9
// speedup vs baseline: 1.3084x; 1.3084x over previous
#include <cuda_runtime.h>
#include <cuda_bf16.h>
#include <math.h>
#include <stdint.h>

#define Bsz 16384
#define Hd  128
#define Cc  4
#define Ll  6
#define NHh 4
#define HDd 32
#define Oo  1024
#define G3H 384

// ---------------- fp32 scratch ----------------------------------------------
__device__ __align__(256) float g_gi [(size_t)Cc * Bsz * G3H];
__device__ __align__(256) float g_gh [(size_t)Cc * Bsz * G3H];
__device__ __align__(256) float g_qkv[(size_t)Cc * Bsz * G3H];
__device__ __align__(256) float g_hn [(size_t)Cc * Bsz * Hd];
__device__ __align__(256) float g_msg[(size_t)Cc * Bsz * Hd];

// ---------------- bf16 hi/lo split buffers ----------------------------------
__device__ __align__(256) __nv_bfloat16 g_x0h[(size_t)Bsz * Hd];
__device__ __align__(256) __nv_bfloat16 g_x0l[(size_t)Bsz * Hd];
__device__ __align__(256) __nv_bfloat16 g_hh [(size_t)Ll * Cc * Bsz * Hd];  // h_in split
__device__ __align__(256) __nv_bfloat16 g_hl [(size_t)Ll * Cc * Bsz * Hd];
__device__ __align__(256) __nv_bfloat16 g_nh [(size_t)Cc * Bsz * Hd];       // hn split
__device__ __align__(256) __nv_bfloat16 g_nl [(size_t)Cc * Bsz * Hd];
__device__ __align__(256) __nv_bfloat16 g_aah[(size_t)Cc * Bsz * Hd];       // att split
__device__ __align__(256) __nv_bfloat16 g_aal[(size_t)Cc * Bsz * Hd];
__device__ __align__(256) __nv_bfloat16 g_ph [(size_t)Cc * Bsz * Hd];       // hOut split
__device__ __align__(256) __nv_bfloat16 g_pl [(size_t)Cc * Bsz * Hd];
// weights
__device__ __align__(256) __nv_bfloat16 g_wih0h[(size_t)G3H * Hd];
__device__ __align__(256) __nv_bfloat16 g_wih0l[(size_t)G3H * Hd];
__device__ __align__(256) __nv_bfloat16 g_whh0h[(size_t)Cc * G3H * Hd];
__device__ __align__(256) __nv_bfloat16 g_whh0l[(size_t)Cc * G3H * Hd];
__device__ __align__(256) __nv_bfloat16 g_wihh[(size_t)(Ll-1) * Cc * G3H * Hd];
__device__ __align__(256) __nv_bfloat16 g_wihl[(size_t)(Ll-1) * Cc * G3H * Hd];
__device__ __align__(256) __nv_bfloat16 g_whhh[(size_t)(Ll-1) * Cc * G3H * Hd];
__device__ __align__(256) __nv_bfloat16 g_whhl[(size_t)(Ll-1) * Cc * G3H * Hd];
__device__ __align__(256) __nv_bfloat16 g_aiwh[(size_t)Ll * G3H * Hd];
__device__ __align__(256) __nv_bfloat16 g_aiwl[(size_t)Ll * G3H * Hd];
__device__ __align__(256) __nv_bfloat16 g_aowh[(size_t)Ll * Hd * Hd];
__device__ __align__(256) __nv_bfloat16 g_aowl[(size_t)Ll * Hd * Hd];
__device__ __align__(256) __nv_bfloat16 g_hwh [(size_t)Oo * Hd];
__device__ __align__(256) __nv_bfloat16 g_hwl [(size_t)Oo * Hd];

__device__ __forceinline__ float sigf(float x) { return 1.0f / (1.0f + expf(-x)); }

__device__ __forceinline__ uint32_t pack_bf16(__nv_bfloat16 a, __nv_bfloat16 b) {
    __nv_bfloat162 t = __nv_bfloat162(a, b);
    return *reinterpret_cast<uint32_t*>(&t);
}

__device__ __forceinline__ void store_split4(__nv_bfloat16* ph, __nv_bfloat16* pl,
                                             long off, float4 v) {
    __nv_bfloat16 h0 = __float2bfloat16(v.x);
    __nv_bfloat16 h1 = __float2bfloat16(v.y);
    __nv_bfloat16 h2 = __float2bfloat16(v.z);
    __nv_bfloat16 h3 = __float2bfloat16(v.w);
    *reinterpret_cast<uint2*>(ph + off) =
        make_uint2(pack_bf16(h0, h1), pack_bf16(h2, h3));
    __nv_bfloat16 l0 = __float2bfloat16(v.x - __bfloat162float(h0));
    __nv_bfloat16 l1 = __float2bfloat16(v.y - __bfloat162float(h1));
    __nv_bfloat16 l2 = __float2bfloat16(v.z - __bfloat162float(h2));
    __nv_bfloat16 l3 = __float2bfloat16(v.w - __bfloat162float(h3));
    *reinterpret_cast<uint2*>(pl + off) =
        make_uint2(pack_bf16(l0, l1), pack_bf16(l2, l3));
}

// ---------------- generic fp32 -> bf16 hi/lo split pass ---------------------
__global__ void split_pair(const float* __restrict__ in, __nv_bfloat16* __restrict__ oh,
                           __nv_bfloat16* __restrict__ ol)
{
    long i = (long)blockIdx.x * 256 + threadIdx.x;   // float4 index
    float4 v = reinterpret_cast<const float4*>(in)[i];
    store_split4(oh, ol, i * 4, v);
}

// ======================= HMMA (mma.sync) GEMM =======================
// R6 config: CTA tile 128(b) x 64(g), 256 threads, 8 warps (4m x 2n),
// warp tile 32x32, 2 CTAs/SM. Term-major MMA ordering for acc-RAW ILP.

#define KPAD    136
#define ROWB    (KPAD * 2)            // 272 bytes per row
#define TILE_A  ((size_t)128 * ROWB)
#define TILE_Bt ((size_t)64  * ROWB)
#define SM_AH   0
#define SM_AL   (SM_AH + TILE_A)
#define SM_BH   (SM_AL + TILE_A)
#define SM_BL   (SM_BH + TILE_Bt)
#define SM_TOT  (SM_BL + TILE_Bt)     // 104448 bytes

__device__ __forceinline__ uint32_t smem_u32(const void* p) {
    uint32_t a;
    asm("{ .reg .u64 t; cvta.to.shared.u64 t, %1; cvt.u32.u64 %0, t; }" : "=r"(a) : "l"(p));
    return a;
}
__device__ __forceinline__ void cpa16(uint32_t sdst, const void* gsrc) {
    asm volatile("cp.async.cg.shared.global [%0], [%1], 16;" :: "r"(sdst), "l"(gsrc));
}
#define CP_COMMIT() asm volatile("cp.async.commit_group;" ::: "memory")
#define CP_WAIT0()  asm volatile("cp.async.wait_group 0;" ::: "memory")

__device__ __forceinline__ void mma16816(float* c, const uint32_t* a, const uint32_t* b) {
    asm volatile(
        "mma.sync.aligned.m16n8k16.row.col.f32.bf16.bf16.f32 "
        "{%0,%1,%2,%3}, {%4,%5,%6,%7}, {%8,%9}, {%0,%1,%2,%3};\n"
        : "+f"(c[0]), "+f"(c[1]), "+f"(c[2]), "+f"(c[3])
        : "r"(a[0]), "r"(a[1]), "r"(a[2]), "r"(a[3]), "r"(b[0]), "r"(b[1]));
}

#define LDSM_X4(r0, r1, r2, r3, addr) \
    asm volatile("ldmatrix.sync.aligned.m8n8.x4.shared.b16 {%0,%1,%2,%3}, [%4];" \
                 : "=r"(r0), "=r"(r1), "=r"(r2), "=r"(r3) : "r"(addr))

struct Frags {
    uint32_t ah[2][4];
    uint32_t al[2][4];
    uint32_t bh[4][2];
    uint32_t bl[4][2];
};

__device__ __forceinline__ void ld_frags(Frags& f, uint32_t aH, uint32_t aL,
                                         uint32_t bH, uint32_t bL) {
    #pragma unroll
    for (int i = 0; i < 2; i++)
        LDSM_X4(f.ah[i][0], f.ah[i][1], f.ah[i][2], f.ah[i][3], aH + i * (16 * ROWB));
    #pragma unroll
    for (int i = 0; i < 2; i++)
        LDSM_X4(f.al[i][0], f.al[i][1], f.al[i][2], f.al[i][3], aL + i * (16 * ROWB));
    LDSM_X4(f.bh[0][0], f.bh[0][1], f.bh[1][0], f.bh[1][1], bH);
    LDSM_X4(f.bh[2][0], f.bh[2][1], f.bh[3][0], f.bh[3][1], bH + 16 * ROWB);
    LDSM_X4(f.bl[0][0], f.bl[0][1], f.bl[1][0], f.bl[1][1], bL);
    LDSM_X4(f.bl[2][0], f.bl[2][1], f.bl[3][0], f.bl[3][1], bL + 16 * ROWB);
}

// shared GEMM body: fill smem, mainloop (term-major), epilogue
__device__ __forceinline__ void gemm_body(
    char* smem,
    const __nv_bfloat16* __restrict__ a_h, const __nv_bfloat16* __restrict__ a_l,
    const __nv_bfloat16* __restrict__ b_h, const __nv_bfloat16* __restrict__ b_l,
    const float* __restrict__ bias, float* __restrict__ Y,
    int G, int b0, int g0)
{
    int tid  = threadIdx.x;
    int wid  = tid >> 5;
    int lane = tid & 31;
    uint32_t sb = smem_u32(smem);

    #pragma unroll 2
    for (int idx = tid; idx < 2048; idx += 256) {
        int r = idx >> 4, k = idx & 15;
        cpa16(sb + SM_AH + r * ROWB + k * 16, a_h + (long)r * 128 + k * 8);
        cpa16(sb + SM_AL + r * ROWB + k * 16, a_l + (long)r * 128 + k * 8);
    }
    #pragma unroll 2
    for (int idx = tid; idx < 1024; idx += 256) {
        int r = idx >> 4, k = idx & 15;
        cpa16(sb + SM_BH + r * ROWB + k * 16, b_h + (long)r * 128 + k * 8);
        cpa16(sb + SM_BL + r * ROWB + k * 16, b_l + (long)r * 128 + k * 8);
    }
    CP_COMMIT();
    CP_WAIT0();
    __syncthreads();

    int wm = (wid & 3) * 32;
    int wn = (wid >> 2) * 32;

    int a_lane = (wm + (lane & 7) + ((lane >> 3) & 1) * 8) * ROWB + (lane >> 4) * 16;
    int b_lane = (wn + (lane & 7) + ((lane >> 4) & 1) * 8) * ROWB + ((lane >> 3) & 1) * 16;

    uint32_t aH = sb + SM_AH + a_lane;
    uint32_t aL = sb + SM_AL + a_lane;
    uint32_t bH = sb + SM_BH + b_lane;
    uint32_t bL = sb + SM_BL + b_lane;

    float acc[2][4][4];
    #pragma unroll
    for (int i = 0; i < 2; i++)
        #pragma unroll
        for (int j = 0; j < 4; j++)
            #pragma unroll
            for (int r = 0; r < 4; r++) acc[i][j][r] = 0.0f;

    Frags fr[2];
    ld_frags(fr[0], aH, aL, bH, bL);

    #pragma unroll
    for (int kk = 0; kk < 8; kk++) {
        if (kk < 7) {
            int ko = (kk + 1) * 32;
            ld_frags(fr[(kk + 1) & 1], aH + ko, aL + ko, bH + ko, bL + ko);
        }
        Frags& f = fr[kk & 1];
        // term-major: 8 independent MMAs between accumulator reuses
        #pragma unroll
        for (int i = 0; i < 2; i++)
            #pragma unroll
            for (int j = 0; j < 4; j++)
                mma16816(acc[i][j], f.ah[i], f.bh[j]);
        #pragma unroll
        for (int i = 0; i < 2; i++)
            #pragma unroll
            for (int j = 0; j < 4; j++)
                mma16816(acc[i][j], f.ah[i], f.bl[j]);
        #pragma unroll
        for (int i = 0; i < 2; i++)
            #pragma unroll
            for (int j = 0; j < 4; j++)
                mma16816(acc[i][j], f.al[i], f.bh[j]);
    }

    int colb = g0 + wn + (lane & 3) * 2;
    #pragma unroll
    for (int i = 0; i < 2; i++) {
        int row = b0 + wm + i * 16 + (lane >> 2);
        #pragma unroll
        for (int j = 0; j < 4; j++) {
            int col = colb + j * 8;
            float bx = bias[col], by = bias[col + 1];
            float2 o0 = make_float2(acc[i][j][0] + bx, acc[i][j][1] + by);
            float2 o1 = make_float2(acc[i][j][2] + bx, acc[i][j][3] + by);
            *reinterpret_cast<float2*>(Y + (long)row * G + col)       = o0;
            *reinterpret_cast<float2*>(Y + (long)(row + 8) * G + col) = o1;
        }
    }
}

__global__ __launch_bounds__(256, 2) void gemm_tc(
    const __nv_bfloat16* __restrict__ Ah, const __nv_bfloat16* __restrict__ Al,
    const __nv_bfloat16* __restrict__ Bh, const __nv_bfloat16* __restrict__ Bl,
    const float* __restrict__ bias, float* __restrict__ Y,
    int G, long xStride, long wStride, long bStride, long yStride)
{
    extern __shared__ char smem[];
    int c = blockIdx.z;
    int b0 = blockIdx.x * 128;
    int g0 = blockIdx.y * 64;
    gemm_body(smem,
              Ah + (long)c * xStride + (long)b0 * 128,
              Al + (long)c * xStride + (long)b0 * 128,
              Bh + (long)c * wStride + (long)g0 * 128,
              Bl + (long)c * wStride + (long)g0 * 128,
              bias + (long)c * bStride,
              Y + (long)c * yStride, G, b0, g0);
}

// dual-set GEMM: z in [0, 2*Cc); z<Cc -> set1 (gi), else set2 (gh).
__global__ __launch_bounds__(256, 2) void gemm_tc_dual(
    const __nv_bfloat16* __restrict__ A1h, const __nv_bfloat16* __restrict__ A1l,
    const __nv_bfloat16* __restrict__ W1h, const __nv_bfloat16* __restrict__ W1l,
    const float* __restrict__ b1, float* __restrict__ Y1,
    const __nv_bfloat16* __restrict__ A2h, const __nv_bfloat16* __restrict__ A2l,
    const __nv_bfloat16* __restrict__ W2h, const __nv_bfloat16* __restrict__ W2l,
    const float* __restrict__ b2, float* __restrict__ Y2)
{
    extern __shared__ char smem[];
    int z  = blockIdx.z;
    int b0 = blockIdx.x * 128;
    int g0 = blockIdx.y * 64;
    const __nv_bfloat16 *ah, *al, *wh, *wl;
    const float* bias;
    float* Y;
    if (z < Cc) {
        int c = z;
        ah = A1h + (long)c * Bsz * Hd;      al = A1l + (long)c * Bsz * Hd;
        wh = W1h + (long)c * G3H * Hd;      wl = W1l + (long)c * G3H * Hd;
        bias = b1 + (long)c * G3H;          Y = Y1 + (long)c * Bsz * G3H;
    } else {
        int c = z - Cc;
        ah = A2h + (long)c * Bsz * Hd;      al = A2l + (long)c * Bsz * Hd;
        wh = W2h + (long)c * G3H * Hd;      wl = W2l + (long)c * G3H * Hd;
        bias = b2 + (long)c * G3H;          Y = Y2 + (long)c * Bsz * G3H;
    }
    gemm_body(smem, ah + (long)b0 * 128, al + (long)b0 * 128,
              wh + (long)g0 * 128, wl + (long)g0 * 128,
              bias, Y, G3H, b0, g0);
}

// ---------------- embedding gather -> bf16 hi/lo split -----------------------
__global__ void gather_x0(const int* __restrict__ tok, const float* __restrict__ emb)
{
    long t = (long)blockIdx.x * 256 + threadIdx.x;   // B*32 threads
    int b  = (int)(t >> 5);
    int e4 = (int)(t & 31) << 2;
    float4 v = *(const float4*)(emb + (long)tok[b] * 128 + e4);
    store_split4(g_x0h, g_x0l, (long)b * 128 + e4, v);
}

// ---------------- l=0 cells 1..3: gi = bias broadcast -----------------------
__global__ void fill_gi0(const float* __restrict__ bih0)
{
    long t = (long)blockIdx.x * 256 + threadIdx.x;
    int  g4  = (int)(t % 96) * 4;
    long rem = t / 96;
    int  b   = (int)(rem % Bsz);
    int  c   = 1 + (int)(rem / Bsz);
    float4 v = *(const float4*)(bih0 + (long)c * G3H + g4);
    *(float4*)(g_gi + ((long)c * Bsz + b) * G3H + g4) = v;
}

// ---------------- GRU elementwise: writes fp32 hn + bf16 split --------------
__global__ void gru_kernel(const float* __restrict__ hprev)
{
    long t   = (long)blockIdx.x * 256 + threadIdx.x;
    long row = t >> 5;
    int  h4  = (int)(t & 31) << 2;
    const float* gi = g_gi + row * G3H;
    const float* gh = g_gh + row * G3H;

    float4 ir  = *(const float4*)(gi + h4);
    float4 iz  = *(const float4*)(gi + 128 + h4);
    float4 inn = *(const float4*)(gi + 256 + h4);
    float4 hr  = *(const float4*)(gh + h4);
    float4 hz  = *(const float4*)(gh + 128 + h4);
    float4 hnn = *(const float4*)(gh + 256 + h4);
    float4 hp  = *(const float4*)(hprev + row * 128 + h4);

    float4 out;
    {
        float r = sigf(ir.x + hr.x), z = sigf(iz.x + hz.x);
        float n = tanhf(inn.x + r * hnn.x);
        out.x = (1.0f - z) * n + z * hp.x;
    }
    {
        float r = sigf(ir.y + hr.y), z = sigf(iz.y + hz.y);
        float n = tanhf(inn.y + r * hnn.y);
        out.y = (1.0f - z) * n + z * hp.y;
    }
    {
        float r = sigf(ir.z + hr.z), z = sigf(iz.z + hz.z);
        float n = tanhf(inn.z + r * hnn.z);
        out.z = (1.0f - z) * n + z * hp.z;
    }
    {
        float r = sigf(ir.w + hr.w), z = sigf(iz.w + hz.w);
        float n = tanhf(inn.w + r * hnn.w);
        out.w = (1.0f - z) * n + z * hp.w;
    }
    long off = row * 128 + h4;
    *(float4*)(g_hn + off) = out;
    store_split4(g_nh, g_nl, off, out);
}

// ---------------- tiny attention over C=4 positions -> bf16 split ------------
__global__ void attn_kernel()
{
    int gw   = blockIdx.x * 4 + (threadIdx.x >> 5);
    int lane = threadIdx.x & 31;
    int b  = gw >> 2;
    int nh = gw & 3;

    float q[4], k[4], v[4];
    #pragma unroll
    for (int c = 0; c < 4; c++) {
        const float* p = g_qkv + ((long)c * Bsz + b) * G3H + nh * 32 + lane;
        q[c] = p[0];
        k[c] = p[128];
        v[c] = p[256];
    }

    float s[4][4];
    #pragma unroll
    for (int qc = 0; qc < 4; qc++) {
        #pragma unroll
        for (int kc = 0; kc < 4; kc++) {
            float p = q[qc] * k[kc];
            #pragma unroll
            for (int off = 16; off > 0; off >>= 1)
                p += __shfl_xor_sync(0xFFFFFFFFu, p, off);
            s[qc][kc] = p * 0.17677669529663687f;   // 1/sqrt(32)
        }
    }

    #pragma unroll
    for (int qc = 0; qc < 4; qc++) {
        float m = fmaxf(fmaxf(s[qc][0], s[qc][1]), fmaxf(s[qc][2], s[qc][3]));
        float e0 = expf(s[qc][0] - m), e1 = expf(s[qc][1] - m);
        float e2 = expf(s[qc][2] - m), e3 = expf(s[qc][3] - m);
        float inv = 1.0f / (e0 + e1 + e2 + e3);
        float o = (e0 * v[0] + e1 * v[1] + e2 * v[2] + e3 * v[3]) * inv;
        long off = ((long)qc * Bsz + b) * 128 + nh * 32 + lane;
        __nv_bfloat16 h = __float2bfloat16(o);
        g_aah[off] = h;
        g_aal[off] = __float2bfloat16(o - __bfloat162float(h));
    }
}

// ---------------- fused LayerNorm + gate + blend -----------------------------
__global__ void lngate_kernel(const float* __restrict__ gg, const float* __restrict__ bb,
                              const float* __restrict__ gw, const float* __restrict__ gbp,
                              float* __restrict__ hout)
{
    int row  = blockIdx.x * 4 + (threadIdx.x >> 5);
    int lane = threadIdx.x & 31;
    const float* mp = g_msg + (long)row * 128;
    const float* hp = g_hn  + (long)row * 128;

    float4 x = *(const float4*)(mp + lane * 4);
    float s = x.x + x.y + x.z + x.w;
    #pragma unroll
    for (int off = 16; off > 0; off >>= 1) s += __shfl_xor_sync(0xFFFFFFFFu, s, off);
    float mean = s * (1.0f / 128.0f);

    float dx = x.x - mean, dy = x.y - mean, dz = x.z - mean, dw = x.w - mean;
    float sq = dx * dx + dy * dy + dz * dz + dw * dw;
    #pragma unroll
    for (int off = 16; off > 0; off >>= 1) sq += __shfl_xor_sync(0xFFFFFFFFu, sq, off);
    float rstd = rsqrtf(sq * (1.0f / 128.0f) + 1e-5f);

    float4 gv = *(const float4*)(gg + lane * 4);
    float4 bv = *(const float4*)(bb + lane * 4);
    float4 m;
    m.x = dx * rstd * gv.x + bv.x;
    m.y = dy * rstd * gv.y + bv.y;
    m.z = dz * rstd * gv.z + bv.z;
    m.w = dw * rstd * gv.w + bv.w;

    float4 hv = *(const float4*)(hp + lane * 4);
    float4 w1 = *(const float4*)(gw + lane * 4);
    float4 w2 = *(const float4*)(gw + 128 + lane * 4);

    float p = hv.x * w1.x + hv.y * w1.y + hv.z * w1.z + hv.w * w1.w
            + m.x * w2.x + m.y * w2.y + m.z * w2.z + m.w * w2.w;
    #pragma unroll
    for (int off = 16; off > 0; off >>= 1) p += __shfl_xor_sync(0xFFFFFFFFu, p, off);
    float gt = sigf(p + gbp[0]);

    float4 o;
    o.x = (1.0f - gt) * hv.x + gt * m.x;
    o.y = (1.0f - gt) * hv.y + gt * m.y;
    o.z = (1.0f - gt) * hv.z + gt * m.z;
    o.w = (1.0f - gt) * hv.w + gt * m.w;
    long off = (long)row * 128 + lane * 4;
    *(float4*)(hout + off) = o;
    store_split4(g_ph, g_pl, off, o);
}

// ---------------- host orchestration ----------------------------------------
extern "C" void kernel_launch(void* const* d_in, const int* in_sizes, int n_in,
                              void* d_out, int out_size)
{
    const int*   tokens     = (const int*)  d_in[0];
    const float* h_in       = (const float*)d_in[1];
    const float* emb        = (const float*)d_in[2];
    const float* wih0_c0    = (const float*)d_in[3];
    const float* bih0       = (const float*)d_in[5];
    const float* whh0       = (const float*)d_in[6];
    const float* bhh0       = (const float*)d_in[7];
    const float* wih        = (const float*)d_in[8];
    const float* whh        = (const float*)d_in[9];
    const float* bih        = (const float*)d_in[10];
    const float* bhh        = (const float*)d_in[11];
    const float* attn_in_w  = (const float*)d_in[12];
    const float* attn_in_b  = (const float*)d_in[13];
    const float* attn_out_w = (const float*)d_in[14];
    const float* attn_out_b = (const float*)d_in[15];
    const float* ln_g       = (const float*)d_in[16];
    const float* ln_b       = (const float*)d_in[17];
    const float* gate_w     = (const float*)d_in[18];
    const float* gate_b     = (const float*)d_in[19];
    const float* head_w     = (const float*)d_in[20];
    const float* head_b     = (const float*)d_in[21];

    float* yOut = (float*)d_out;                       // (B, O)
    float* hOut = yOut + (size_t)Bsz * Oo;             // (L, C, B, H)

    float *pgi, *pgh, *pqkv, *pmsg;
    cudaGetSymbolAddress((void**)&pgi,  g_gi);
    cudaGetSymbolAddress((void**)&pgh,  g_gh);
    cudaGetSymbolAddress((void**)&pqkv, g_qkv);
    cudaGetSymbolAddress((void**)&pmsg, g_msg);

    __nv_bfloat16 *x0h, *x0l, *hh, *hl, *nh, *nl, *aah, *aal, *ph, *pl;
    __nv_bfloat16 *wih0h, *wih0l, *whh0h, *whh0l, *wihh, *wihl, *whhh, *whhl;
    __nv_bfloat16 *aiwh, *aiwl, *aowh, *aowl, *hwh, *hwl;
    cudaGetSymbolAddress((void**)&x0h, g_x0h);   cudaGetSymbolAddress((void**)&x0l, g_x0l);
    cudaGetSymbolAddress((void**)&hh,  g_hh);    cudaGetSymbolAddress((void**)&hl,  g_hl);
    cudaGetSymbolAddress((void**)&nh,  g_nh);    cudaGetSymbolAddress((void**)&nl,  g_nl);
    cudaGetSymbolAddress((void**)&aah, g_aah);   cudaGetSymbolAddress((void**)&aal, g_aal);
    cudaGetSymbolAddress((void**)&ph,  g_ph);    cudaGetSymbolAddress((void**)&pl,  g_pl);
    cudaGetSymbolAddress((void**)&wih0h, g_wih0h); cudaGetSymbolAddress((void**)&wih0l, g_wih0l);
    cudaGetSymbolAddress((void**)&whh0h, g_whh0h); cudaGetSymbolAddress((void**)&whh0l, g_whh0l);
    cudaGetSymbolAddress((void**)&wihh, g_wihh); cudaGetSymbolAddress((void**)&wihl, g_wihl);
    cudaGetSymbolAddress((void**)&whhh, g_whhh); cudaGetSymbolAddress((void**)&whhl, g_whhl);
    cudaGetSymbolAddress((void**)&aiwh, g_aiwh); cudaGetSymbolAddress((void**)&aiwl, g_aiwl);
    cudaGetSymbolAddress((void**)&aowh, g_aowh); cudaGetSymbolAddress((void**)&aowl, g_aowl);
    cudaGetSymbolAddress((void**)&hwh,  g_hwh);  cudaGetSymbolAddress((void**)&hwl,  g_hwl);

    cudaFuncSetAttribute(gemm_tc,      cudaFuncAttributeMaxDynamicSharedMemorySize, SM_TOT);
    cudaFuncSetAttribute(gemm_tc_dual, cudaFuncAttributeMaxDynamicSharedMemorySize, SM_TOT);

    const long CBH = (long)Cc * Bsz * Hd;
    (void)in_sizes; (void)n_in; (void)out_size;

    // ---- prolog: split weights + h into bf16 hi/lo ----
    #define SPLIT(src, dh, dl, nelem) \
        split_pair<<<(int)((nelem) / 1024), 256>>>(src, dh, dl)
    SPLIT(wih0_c0,   wih0h, wih0l, (long)G3H * Hd);
    SPLIT(whh0,      whh0h, whh0l, (long)Cc * G3H * Hd);
    SPLIT(wih,       wihh,  wihl,  (long)(Ll-1) * Cc * G3H * Hd);
    SPLIT(whh,       whhh,  whhl,  (long)(Ll-1) * Cc * G3H * Hd);
    SPLIT(attn_in_w, aiwh,  aiwl,  (long)Ll * G3H * Hd);
    SPLIT(attn_out_w,aowh,  aowl,  (long)Ll * Hd * Hd);
    SPLIT(head_w,    hwh,   hwl,   (long)Oo * Hd);
    SPLIT(h_in,      hh,    hl,    (long)Ll * CBH);
    #undef SPLIT
    gather_x0<<<(Bsz * 32) / 256, 256>>>(tokens, emb);

    dim3 gB(Bsz / 128, G3H / 64, Cc);
    dim3 gD(Bsz / 128, G3H / 64, 2 * Cc);
    dim3 gO(Bsz / 128, Hd  / 64, Cc);

    for (int l = 0; l < Ll; l++) {
        const float* hlp = h_in + (size_t)l * CBH;

        // ---- gi + gh ----
        if (l == 0) {
            dim3 g1(Bsz / 128, G3H / 64, 1);
            gemm_tc<<<g1, 256, SM_TOT>>>(x0h, x0l, wih0h, wih0l, bih0, pgi,
                                         G3H, 0, 0, 0, 0);
            fill_gi0<<<(3 * Bsz * 96) / 256, 256>>>(bih0);
            gemm_tc<<<gB, 256, SM_TOT>>>(hh, hl, whh0h, whh0l, bhh0, pgh, G3H,
                                         (long)Bsz * Hd, (long)G3H * Hd, G3H,
                                         (long)Bsz * G3H);
        } else {
            gemm_tc_dual<<<gD, 256, SM_TOT>>>(
                ph, pl,
                wihh + (size_t)(l - 1) * Cc * G3H * Hd,
                wihl + (size_t)(l - 1) * Cc * G3H * Hd,
                bih + (size_t)(l - 1) * Cc * G3H, pgi,
                hh + (size_t)l * CBH, hl + (size_t)l * CBH,
                whhh + (size_t)(l - 1) * Cc * G3H * Hd,
                whhl + (size_t)(l - 1) * Cc * G3H * Hd,
                bhh + (size_t)(l - 1) * Cc * G3H, pgh);
        }

        // ---- GRU ----
        gru_kernel<<<((long)Cc * Bsz * 32) / 256, 256>>>(hlp);

        // ---- QKV ----
        gemm_tc<<<gB, 256, SM_TOT>>>(nh, nl,
                                     aiwh + (size_t)l * G3H * Hd,
                                     aiwl + (size_t)l * G3H * Hd,
                                     attn_in_b + (size_t)l * G3H,
                                     pqkv, G3H,
                                     (long)Bsz * Hd, 0, 0, (long)Bsz * G3H);

        // ---- attention ----
        attn_kernel<<<(Bsz * NHh) / 4, 128>>>();

        // ---- out projection ----
        gemm_tc<<<gO, 256, SM_TOT>>>(aah, aal,
                                     aowh + (size_t)l * Hd * Hd,
                                     aowl + (size_t)l * Hd * Hd,
                                     attn_out_b + (size_t)l * Hd,
                                     pmsg, Hd,
                                     (long)Bsz * Hd, 0, 0, (long)Bsz * Hd);

        // ---- fused LN + gate + blend -> hOut + g_ph/g_pl split ----
        lngate_kernel<<<(Cc * Bsz) / 4, 128>>>(ln_g + (size_t)l * Hd, ln_b + (size_t)l * Hd,
                                               gate_w + (size_t)l * 2 * Hd, gate_b + l,
                                               hOut + (size_t)l * CBH);
    }

    // ---- head: y = h_n[L-1, 0] @ head_w.T + head_b ----
    dim3 gH(Bsz / 128, Oo / 64, 1);
    gemm_tc<<<gH, 256, SM_TOT>>>(ph, pl, hwh, hwl, head_b, yOut, Oo, 0, 0, 0, 0);
}

// round 10
// speedup vs baseline: 1.3835x; 1.0574x over previous
#include <cuda_runtime.h>
#include <cuda_bf16.h>
#include <math.h>
#include <stdint.h>

#define Bsz 16384
#define Hd  128
#define Cc  4
#define Ll  6
#define NHh 4
#define HDd 32
#define Oo  1024
#define G3H 384

// ---------------- fp32 scratch ----------------------------------------------
__device__ __align__(256) float g_gi [(size_t)Cc * Bsz * G3H];
__device__ __align__(256) float g_gh [(size_t)Cc * Bsz * G3H];
__device__ __align__(256) float g_qkv[(size_t)Cc * Bsz * G3H];
__device__ __align__(256) float g_hn [(size_t)Cc * Bsz * Hd];
__device__ __align__(256) float g_msg[(size_t)Cc * Bsz * Hd];

// ---------------- bf16 hi/lo split buffers ----------------------------------
__device__ __align__(256) __nv_bfloat16 g_x0h[(size_t)Bsz * Hd];
__device__ __align__(256) __nv_bfloat16 g_x0l[(size_t)Bsz * Hd];
__device__ __align__(256) __nv_bfloat16 g_hh [(size_t)Ll * Cc * Bsz * Hd];  // h_in split
__device__ __align__(256) __nv_bfloat16 g_hl [(size_t)Ll * Cc * Bsz * Hd];
__device__ __align__(256) __nv_bfloat16 g_nh [(size_t)Cc * Bsz * Hd];       // hn split
__device__ __align__(256) __nv_bfloat16 g_nl [(size_t)Cc * Bsz * Hd];
__device__ __align__(256) __nv_bfloat16 g_aah[(size_t)Cc * Bsz * Hd];       // att split
__device__ __align__(256) __nv_bfloat16 g_aal[(size_t)Cc * Bsz * Hd];
__device__ __align__(256) __nv_bfloat16 g_ph [(size_t)Cc * Bsz * Hd];       // hOut split
__device__ __align__(256) __nv_bfloat16 g_pl [(size_t)Cc * Bsz * Hd];
// weights
__device__ __align__(256) __nv_bfloat16 g_wih0h[(size_t)G3H * Hd];
__device__ __align__(256) __nv_bfloat16 g_wih0l[(size_t)G3H * Hd];
__device__ __align__(256) __nv_bfloat16 g_whh0h[(size_t)Cc * G3H * Hd];
__device__ __align__(256) __nv_bfloat16 g_whh0l[(size_t)Cc * G3H * Hd];
__device__ __align__(256) __nv_bfloat16 g_wihh[(size_t)(Ll-1) * Cc * G3H * Hd];
__device__ __align__(256) __nv_bfloat16 g_wihl[(size_t)(Ll-1) * Cc * G3H * Hd];
__device__ __align__(256) __nv_bfloat16 g_whhh[(size_t)(Ll-1) * Cc * G3H * Hd];
__device__ __align__(256) __nv_bfloat16 g_whhl[(size_t)(Ll-1) * Cc * G3H * Hd];
__device__ __align__(256) __nv_bfloat16 g_aiwh[(size_t)Ll * G3H * Hd];
__device__ __align__(256) __nv_bfloat16 g_aiwl[(size_t)Ll * G3H * Hd];
__device__ __align__(256) __nv_bfloat16 g_aowh[(size_t)Ll * Hd * Hd];
__device__ __align__(256) __nv_bfloat16 g_aowl[(size_t)Ll * Hd * Hd];
__device__ __align__(256) __nv_bfloat16 g_hwh [(size_t)Oo * Hd];
__device__ __align__(256) __nv_bfloat16 g_hwl [(size_t)Oo * Hd];

__device__ __forceinline__ float sigf(float x) { return 1.0f / (1.0f + expf(-x)); }

__device__ __forceinline__ uint32_t pack_bf16(__nv_bfloat16 a, __nv_bfloat16 b) {
    __nv_bfloat162 t = __nv_bfloat162(a, b);
    return *reinterpret_cast<uint32_t*>(&t);
}

__device__ __forceinline__ void store_split4(__nv_bfloat16* ph, __nv_bfloat16* pl,
                                             long off, float4 v) {
    __nv_bfloat16 h0 = __float2bfloat16(v.x);
    __nv_bfloat16 h1 = __float2bfloat16(v.y);
    __nv_bfloat16 h2 = __float2bfloat16(v.z);
    __nv_bfloat16 h3 = __float2bfloat16(v.w);
    *reinterpret_cast<uint2*>(ph + off) =
        make_uint2(pack_bf16(h0, h1), pack_bf16(h2, h3));
    __nv_bfloat16 l0 = __float2bfloat16(v.x - __bfloat162float(h0));
    __nv_bfloat16 l1 = __float2bfloat16(v.y - __bfloat162float(h1));
    __nv_bfloat16 l2 = __float2bfloat16(v.z - __bfloat162float(h2));
    __nv_bfloat16 l3 = __float2bfloat16(v.w - __bfloat162float(h3));
    *reinterpret_cast<uint2*>(pl + off) =
        make_uint2(pack_bf16(l0, l1), pack_bf16(l2, l3));
}

// ---------------- generic fp32 -> bf16 hi/lo split pass ---------------------
__global__ void split_pair(const float* __restrict__ in, __nv_bfloat16* __restrict__ oh,
                           __nv_bfloat16* __restrict__ ol)
{
    long i = (long)blockIdx.x * 256 + threadIdx.x;   // float4 index
    float4 v = reinterpret_cast<const float4*>(in)[i];
    store_split4(oh, ol, i * 4, v);
}

// ======================= HMMA (mma.sync) GEMM =======================
// CTA tile 128(b) x 64(g), 256 threads, 8 warps (4m x 2n), warp tile 32x32,
// 2 CTAs/SM. Term-major MMA ordering; 2-stage pipelined k-split fill.

#define KPAD    136
#define ROWB    (KPAD * 2)            // 272 bytes per row
#define TILE_A  ((size_t)128 * ROWB)
#define TILE_Bt ((size_t)64  * ROWB)
#define SM_AH   0
#define SM_AL   (SM_AH + TILE_A)
#define SM_BH   (SM_AL + TILE_A)
#define SM_BL   (SM_BH + TILE_Bt)
#define SM_TOT  (SM_BL + TILE_Bt)     // 104448 bytes

__device__ __forceinline__ uint32_t smem_u32(const void* p) {
    uint32_t a;
    asm("{ .reg .u64 t; cvta.to.shared.u64 t, %1; cvt.u32.u64 %0, t; }" : "=r"(a) : "l"(p));
    return a;
}
__device__ __forceinline__ void cpa16(uint32_t sdst, const void* gsrc) {
    asm volatile("cp.async.cg.shared.global [%0], [%1], 16;" :: "r"(sdst), "l"(gsrc));
}
#define CP_COMMIT() asm volatile("cp.async.commit_group;" ::: "memory")
#define CP_WAIT(n)  asm volatile("cp.async.wait_group %0;" :: "n"(n) : "memory")

__device__ __forceinline__ void mma16816(float* c, const uint32_t* a, const uint32_t* b) {
    asm volatile(
        "mma.sync.aligned.m16n8k16.row.col.f32.bf16.bf16.f32 "
        "{%0,%1,%2,%3}, {%4,%5,%6,%7}, {%8,%9}, {%0,%1,%2,%3};\n"
        : "+f"(c[0]), "+f"(c[1]), "+f"(c[2]), "+f"(c[3])
        : "r"(a[0]), "r"(a[1]), "r"(a[2]), "r"(a[3]), "r"(b[0]), "r"(b[1]));
}

#define LDSM_X4(r0, r1, r2, r3, addr) \
    asm volatile("ldmatrix.sync.aligned.m8n8.x4.shared.b16 {%0,%1,%2,%3}, [%4];" \
                 : "=r"(r0), "=r"(r1), "=r"(r2), "=r"(r3) : "r"(addr))

struct Frags {
    uint32_t ah[2][4];
    uint32_t al[2][4];
    uint32_t bh[4][2];
    uint32_t bl[4][2];
};

__device__ __forceinline__ void ld_frags(Frags& f, uint32_t aH, uint32_t aL,
                                         uint32_t bH, uint32_t bL) {
    #pragma unroll
    for (int i = 0; i < 2; i++)
        LDSM_X4(f.ah[i][0], f.ah[i][1], f.ah[i][2], f.ah[i][3], aH + i * (16 * ROWB));
    #pragma unroll
    for (int i = 0; i < 2; i++)
        LDSM_X4(f.al[i][0], f.al[i][1], f.al[i][2], f.al[i][3], aL + i * (16 * ROWB));
    LDSM_X4(f.bh[0][0], f.bh[0][1], f.bh[1][0], f.bh[1][1], bH);
    LDSM_X4(f.bh[2][0], f.bh[2][1], f.bh[3][0], f.bh[3][1], bH + 16 * ROWB);
    LDSM_X4(f.bl[0][0], f.bl[0][1], f.bl[1][0], f.bl[1][1], bL);
    LDSM_X4(f.bl[2][0], f.bl[2][1], f.bl[3][0], f.bl[3][1], bL + 16 * ROWB);
}

__device__ __forceinline__ void mma_all(float acc[2][4][4], Frags& f) {
    // term-major: 8 independent MMAs between accumulator reuses
    #pragma unroll
    for (int i = 0; i < 2; i++)
        #pragma unroll
        for (int j = 0; j < 4; j++)
            mma16816(acc[i][j], f.ah[i], f.bh[j]);
    #pragma unroll
    for (int i = 0; i < 2; i++)
        #pragma unroll
        for (int j = 0; j < 4; j++)
            mma16816(acc[i][j], f.ah[i], f.bl[j]);
    #pragma unroll
    for (int i = 0; i < 2; i++)
        #pragma unroll
        for (int j = 0; j < 4; j++)
            mma16816(acc[i][j], f.al[i], f.bh[j]);
}

// fill one k-half (chunks [h*8, h*8+8) of 16B per row) for A and B tiles
__device__ __forceinline__ void fill_half(
    uint32_t sb, int tid, int h,
    const __nv_bfloat16* a_h, const __nv_bfloat16* a_l,
    const __nv_bfloat16* b_h, const __nv_bfloat16* b_l)
{
    #pragma unroll 2
    for (int idx = tid; idx < 1024; idx += 256) {        // A: 128 rows x 8 chunks
        int r = idx >> 3, k = (idx & 7) + h * 8;
        cpa16(sb + SM_AH + r * ROWB + k * 16, a_h + (long)r * 128 + k * 8);
        cpa16(sb + SM_AL + r * ROWB + k * 16, a_l + (long)r * 128 + k * 8);
    }
    #pragma unroll 2
    for (int idx = tid; idx < 512; idx += 256) {         // B: 64 rows x 8 chunks
        int r = idx >> 3, k = (idx & 7) + h * 8;
        cpa16(sb + SM_BH + r * ROWB + k * 16, b_h + (long)r * 128 + k * 8);
        cpa16(sb + SM_BL + r * ROWB + k * 16, b_l + (long)r * 128 + k * 8);
    }
}

// shared GEMM body: 2-stage pipelined fill, term-major mainloop, epilogue
__device__ __forceinline__ void gemm_body(
    char* smem,
    const __nv_bfloat16* __restrict__ a_h, const __nv_bfloat16* __restrict__ a_l,
    const __nv_bfloat16* __restrict__ b_h, const __nv_bfloat16* __restrict__ b_l,
    const float* __restrict__ bias, float* __restrict__ Y,
    int G, int b0, int g0)
{
    int tid  = threadIdx.x;
    int wid  = tid >> 5;
    int lane = tid & 31;
    uint32_t sb = smem_u32(smem);

    fill_half(sb, tid, 0, a_h, a_l, b_h, b_l);
    CP_COMMIT();
    fill_half(sb, tid, 1, a_h, a_l, b_h, b_l);
    CP_COMMIT();

    int wm = (wid & 3) * 32;
    int wn = (wid >> 2) * 32;

    int a_lane = (wm + (lane & 7) + ((lane >> 3) & 1) * 8) * ROWB + (lane >> 4) * 16;
    int b_lane = (wn + (lane & 7) + ((lane >> 4) & 1) * 8) * ROWB + ((lane >> 3) & 1) * 16;

    uint32_t aH = sb + SM_AH + a_lane;
    uint32_t aL = sb + SM_AL + a_lane;
    uint32_t bH = sb + SM_BH + b_lane;
    uint32_t bL = sb + SM_BL + b_lane;

    float acc[2][4][4];
    #pragma unroll
    for (int i = 0; i < 2; i++)
        #pragma unroll
        for (int j = 0; j < 4; j++)
            #pragma unroll
            for (int r = 0; r < 4; r++) acc[i][j][r] = 0.0f;

    Frags fr[2];

    // ---- first k-half (steps 0..3) ----
    CP_WAIT(1);
    __syncthreads();
    ld_frags(fr[0], aH, aL, bH, bL);
    #pragma unroll
    for (int kk = 0; kk < 4; kk++) {
        if (kk < 3) {
            int ko = (kk + 1) * 32;
            ld_frags(fr[(kk + 1) & 1], aH + ko, aL + ko, bH + ko, bL + ko);
        }
        mma_all(acc, fr[kk & 1]);
    }

    // ---- second k-half (steps 4..7) ----
    CP_WAIT(0);
    __syncthreads();
    ld_frags(fr[0], aH + 128, aL + 128, bH + 128, bL + 128);
    #pragma unroll
    for (int kk = 0; kk < 4; kk++) {
        if (kk < 3) {
            int ko = 128 + (kk + 1) * 32;
            ld_frags(fr[(kk + 1) & 1], aH + ko, aL + ko, bH + ko, bL + ko);
        }
        mma_all(acc, fr[kk & 1]);
    }

    int colb = g0 + wn + (lane & 3) * 2;
    #pragma unroll
    for (int i = 0; i < 2; i++) {
        int row = b0 + wm + i * 16 + (lane >> 2);
        #pragma unroll
        for (int j = 0; j < 4; j++) {
            int col = colb + j * 8;
            float bx = bias[col], by = bias[col + 1];
            float2 o0 = make_float2(acc[i][j][0] + bx, acc[i][j][1] + by);
            float2 o1 = make_float2(acc[i][j][2] + bx, acc[i][j][3] + by);
            *reinterpret_cast<float2*>(Y + (long)row * G + col)       = o0;
            *reinterpret_cast<float2*>(Y + (long)(row + 8) * G + col) = o1;
        }
    }
}

__global__ __launch_bounds__(256, 2) void gemm_tc(
    const __nv_bfloat16* __restrict__ Ah, const __nv_bfloat16* __restrict__ Al,
    const __nv_bfloat16* __restrict__ Bh, const __nv_bfloat16* __restrict__ Bl,
    const float* __restrict__ bias, float* __restrict__ Y,
    int G, long xStride, long wStride, long bStride, long yStride)
{
    extern __shared__ char smem[];
    int c = blockIdx.z;
    int b0 = blockIdx.x * 128;
    int g0 = blockIdx.y * 64;
    gemm_body(smem,
              Ah + (long)c * xStride + (long)b0 * 128,
              Al + (long)c * xStride + (long)b0 * 128,
              Bh + (long)c * wStride + (long)g0 * 128,
              Bl + (long)c * wStride + (long)g0 * 128,
              bias + (long)c * bStride,
              Y + (long)c * yStride, G, b0, g0);
}

// dual-set GEMM: z in [0, 2*Cc); z<Cc -> set1 (gi), else set2 (gh).
__global__ __launch_bounds__(256, 2) void gemm_tc_dual(
    const __nv_bfloat16* __restrict__ A1h, const __nv_bfloat16* __restrict__ A1l,
    const __nv_bfloat16* __restrict__ W1h, const __nv_bfloat16* __restrict__ W1l,
    const float* __restrict__ b1, float* __restrict__ Y1,
    const __nv_bfloat16* __restrict__ A2h, const __nv_bfloat16* __restrict__ A2l,
    const __nv_bfloat16* __restrict__ W2h, const __nv_bfloat16* __restrict__ W2l,
    const float* __restrict__ b2, float* __restrict__ Y2)
{
    extern __shared__ char smem[];
    int z  = blockIdx.z;
    int b0 = blockIdx.x * 128;
    int g0 = blockIdx.y * 64;
    const __nv_bfloat16 *ah, *al, *wh, *wl;
    const float* bias;
    float* Y;
    if (z < Cc) {
        int c = z;
        ah = A1h + (long)c * Bsz * Hd;      al = A1l + (long)c * Bsz * Hd;
        wh = W1h + (long)c * G3H * Hd;      wl = W1l + (long)c * G3H * Hd;
        bias = b1 + (long)c * G3H;          Y = Y1 + (long)c * Bsz * G3H;
    } else {
        int c = z - Cc;
        ah = A2h + (long)c * Bsz * Hd;      al = A2l + (long)c * Bsz * Hd;
        wh = W2h + (long)c * G3H * Hd;      wl = W2l + (long)c * G3H * Hd;
        bias = b2 + (long)c * G3H;          Y = Y2 + (long)c * Bsz * G3H;
    }
    gemm_body(smem, ah + (long)b0 * 128, al + (long)b0 * 128,
              wh + (long)g0 * 128, wl + (long)g0 * 128,
              bias, Y, G3H, b0, g0);
}

// ---------------- embedding gather -> bf16 hi/lo split -----------------------
__global__ void gather_x0(const int* __restrict__ tok, const float* __restrict__ emb)
{
    long t = (long)blockIdx.x * 256 + threadIdx.x;   // B*32 threads
    int b  = (int)(t >> 5);
    int e4 = (int)(t & 31) << 2;
    float4 v = *(const float4*)(emb + (long)tok[b] * 128 + e4);
    store_split4(g_x0h, g_x0l, (long)b * 128 + e4, v);
}

// ---------------- GRU elementwise: writes fp32 hn + bf16 split --------------
// l0bias != nullptr => layer 0: for cells c>0, gi is pure bias (read directly).
__global__ void gru_kernel(const float* __restrict__ hprev,
                           const float* __restrict__ l0bias)
{
    long t   = (long)blockIdx.x * 256 + threadIdx.x;
    long row = t >> 5;
    int  h4  = (int)(t & 31) << 2;
    int  c   = (int)(row >> 14);      // row / Bsz

    const float* gi;
    if (l0bias != nullptr && c > 0)
        gi = l0bias + (long)c * G3H;          // bias broadcast, no gi buffer
    else
        gi = g_gi + row * G3H;
    const float* gh = g_gh + row * G3H;

    float4 ir  = *(const float4*)(gi + h4);
    float4 iz  = *(const float4*)(gi + 128 + h4);
    float4 inn = *(const float4*)(gi + 256 + h4);
    float4 hr  = *(const float4*)(gh + h4);
    float4 hz  = *(const float4*)(gh + 128 + h4);
    float4 hnn = *(const float4*)(gh + 256 + h4);
    float4 hp  = *(const float4*)(hprev + row * 128 + h4);

    float4 out;
    {
        float r = sigf(ir.x + hr.x), z = sigf(iz.x + hz.x);
        float n = tanhf(inn.x + r * hnn.x);
        out.x = (1.0f - z) * n + z * hp.x;
    }
    {
        float r = sigf(ir.y + hr.y), z = sigf(iz.y + hz.y);
        float n = tanhf(inn.y + r * hnn.y);
        out.y = (1.0f - z) * n + z * hp.y;
    }
    {
        float r = sigf(ir.z + hr.z), z = sigf(iz.z + hz.z);
        float n = tanhf(inn.z + r * hnn.z);
        out.z = (1.0f - z) * n + z * hp.z;
    }
    {
        float r = sigf(ir.w + hr.w), z = sigf(iz.w + hz.w);
        float n = tanhf(inn.w + r * hnn.w);
        out.w = (1.0f - z) * n + z * hp.w;
    }
    long off = row * 128 + h4;
    *(float4*)(g_hn + off) = out;
    store_split4(g_nh, g_nl, off, out);
}

// ---------------- tiny attention over C=4 positions -> bf16 split ------------
__global__ void attn_kernel()
{
    int gw   = blockIdx.x * 4 + (threadIdx.x >> 5);
    int lane = threadIdx.x & 31;
    int b  = gw >> 2;
    int nh = gw & 3;

    float q[4], k[4], v[4];
    #pragma unroll
    for (int c = 0; c < 4; c++) {
        const float* p = g_qkv + ((long)c * Bsz + b) * G3H + nh * 32 + lane;
        q[c] = p[0];
        k[c] = p[128];
        v[c] = p[256];
    }

    float s[4][4];
    #pragma unroll
    for (int qc = 0; qc < 4; qc++) {
        #pragma unroll
        for (int kc = 0; kc < 4; kc++) {
            float p = q[qc] * k[kc];
            #pragma unroll
            for (int off = 16; off > 0; off >>= 1)
                p += __shfl_xor_sync(0xFFFFFFFFu, p, off);
            s[qc][kc] = p * 0.17677669529663687f;   // 1/sqrt(32)
        }
    }

    #pragma unroll
    for (int qc = 0; qc < 4; qc++) {
        float m = fmaxf(fmaxf(s[qc][0], s[qc][1]), fmaxf(s[qc][2], s[qc][3]));
        float e0 = expf(s[qc][0] - m), e1 = expf(s[qc][1] - m);
        float e2 = expf(s[qc][2] - m), e3 = expf(s[qc][3] - m);
        float inv = 1.0f / (e0 + e1 + e2 + e3);
        float o = (e0 * v[0] + e1 * v[1] + e2 * v[2] + e3 * v[3]) * inv;
        long off = ((long)qc * Bsz + b) * 128 + nh * 32 + lane;
        __nv_bfloat16 h = __float2bfloat16(o);
        g_aah[off] = h;
        g_aal[off] = __float2bfloat16(o - __bfloat162float(h));
    }
}

// ---------------- fused LayerNorm + gate + blend -----------------------------
__global__ void lngate_kernel(const float* __restrict__ gg, const float* __restrict__ bb,
                              const float* __restrict__ gw, const float* __restrict__ gbp,
                              float* __restrict__ hout)
{
    int row  = blockIdx.x * 4 + (threadIdx.x >> 5);
    int lane = threadIdx.x & 31;
    const float* mp = g_msg + (long)row * 128;
    const float* hp = g_hn  + (long)row * 128;

    float4 x = *(const float4*)(mp + lane * 4);
    float s = x.x + x.y + x.z + x.w;
    #pragma unroll
    for (int off = 16; off > 0; off >>= 1) s += __shfl_xor_sync(0xFFFFFFFFu, s, off);
    float mean = s * (1.0f / 128.0f);

    float dx = x.x - mean, dy = x.y - mean, dz = x.z - mean, dw = x.w - mean;
    float sq = dx * dx + dy * dy + dz * dz + dw * dw;
    #pragma unroll
    for (int off = 16; off > 0; off >>= 1) sq += __shfl_xor_sync(0xFFFFFFFFu, sq, off);
    float rstd = rsqrtf(sq * (1.0f / 128.0f) + 1e-5f);

    float4 gv = *(const float4*)(gg + lane * 4);
    float4 bv = *(const float4*)(bb + lane * 4);
    float4 m;
    m.x = dx * rstd * gv.x + bv.x;
    m.y = dy * rstd * gv.y + bv.y;
    m.z = dz * rstd * gv.z + bv.z;
    m.w = dw * rstd * gv.w + bv.w;

    float4 hv = *(const float4*)(hp + lane * 4);
    float4 w1 = *(const float4*)(gw + lane * 4);
    float4 w2 = *(const float4*)(gw + 128 + lane * 4);

    float p = hv.x * w1.x + hv.y * w1.y + hv.z * w1.z + hv.w * w1.w
            + m.x * w2.x + m.y * w2.y + m.z * w2.z + m.w * w2.w;
    #pragma unroll
    for (int off = 16; off > 0; off >>= 1) p += __shfl_xor_sync(0xFFFFFFFFu, p, off);
    float gt = sigf(p + gbp[0]);

    float4 o;
    o.x = (1.0f - gt) * hv.x + gt * m.x;
    o.y = (1.0f - gt) * hv.y + gt * m.y;
    o.z = (1.0f - gt) * hv.z + gt * m.z;
    o.w = (1.0f - gt) * hv.w + gt * m.w;
    long off = (long)row * 128 + lane * 4;
    *(float4*)(hout + off) = o;
    store_split4(g_ph, g_pl, off, o);
}

// ---------------- host orchestration ----------------------------------------
extern "C" void kernel_launch(void* const* d_in, const int* in_sizes, int n_in,
                              void* d_out, int out_size)
{
    const int*   tokens     = (const int*)  d_in[0];
    const float* h_in       = (const float*)d_in[1];
    const float* emb        = (const float*)d_in[2];
    const float* wih0_c0    = (const float*)d_in[3];
    const float* bih0       = (const float*)d_in[5];
    const float* whh0       = (const float*)d_in[6];
    const float* bhh0       = (const float*)d_in[7];
    const float* wih        = (const float*)d_in[8];
    const float* whh        = (const float*)d_in[9];
    const float* bih        = (const float*)d_in[10];
    const float* bhh        = (const float*)d_in[11];
    const float* attn_in_w  = (const float*)d_in[12];
    const float* attn_in_b  = (const float*)d_in[13];
    const float* attn_out_w = (const float*)d_in[14];
    const float* attn_out_b = (const float*)d_in[15];
    const float* ln_g       = (const float*)d_in[16];
    const float* ln_b       = (const float*)d_in[17];
    const float* gate_w     = (const float*)d_in[18];
    const float* gate_b     = (const float*)d_in[19];
    const float* head_w     = (const float*)d_in[20];
    const float* head_b     = (const float*)d_in[21];

    float* yOut = (float*)d_out;                       // (B, O)
    float* hOut = yOut + (size_t)Bsz * Oo;             // (L, C, B, H)

    float *pgi, *pgh, *pqkv, *pmsg;
    cudaGetSymbolAddress((void**)&pgi,  g_gi);
    cudaGetSymbolAddress((void**)&pgh,  g_gh);
    cudaGetSymbolAddress((void**)&pqkv, g_qkv);
    cudaGetSymbolAddress((void**)&pmsg, g_msg);

    __nv_bfloat16 *x0h, *x0l, *hh, *hl, *nh, *nl, *aah, *aal, *ph, *pl;
    __nv_bfloat16 *wih0h, *wih0l, *whh0h, *whh0l, *wihh, *wihl, *whhh, *whhl;
    __nv_bfloat16 *aiwh, *aiwl, *aowh, *aowl, *hwh, *hwl;
    cudaGetSymbolAddress((void**)&x0h, g_x0h);   cudaGetSymbolAddress((void**)&x0l, g_x0l);
    cudaGetSymbolAddress((void**)&hh,  g_hh);    cudaGetSymbolAddress((void**)&hl,  g_hl);
    cudaGetSymbolAddress((void**)&nh,  g_nh);    cudaGetSymbolAddress((void**)&nl,  g_nl);
    cudaGetSymbolAddress((void**)&aah, g_aah);   cudaGetSymbolAddress((void**)&aal, g_aal);
    cudaGetSymbolAddress((void**)&ph,  g_ph);    cudaGetSymbolAddress((void**)&pl,  g_pl);
    cudaGetSymbolAddress((void**)&wih0h, g_wih0h); cudaGetSymbolAddress((void**)&wih0l, g_wih0l);
    cudaGetSymbolAddress((void**)&whh0h, g_whh0h); cudaGetSymbolAddress((void**)&whh0l, g_whh0l);
    cudaGetSymbolAddress((void**)&wihh, g_wihh); cudaGetSymbolAddress((void**)&wihl, g_wihl);
    cudaGetSymbolAddress((void**)&whhh, g_whhh); cudaGetSymbolAddress((void**)&whhl, g_whhl);
    cudaGetSymbolAddress((void**)&aiwh, g_aiwh); cudaGetSymbolAddress((void**)&aiwl, g_aiwl);
    cudaGetSymbolAddress((void**)&aowh, g_aowh); cudaGetSymbolAddress((void**)&aowl, g_aowl);
    cudaGetSymbolAddress((void**)&hwh,  g_hwh);  cudaGetSymbolAddress((void**)&hwl,  g_hwl);

    cudaFuncSetAttribute(gemm_tc,      cudaFuncAttributeMaxDynamicSharedMemorySize, SM_TOT);
    cudaFuncSetAttribute(gemm_tc_dual, cudaFuncAttributeMaxDynamicSharedMemorySize, SM_TOT);

    const long CBH = (long)Cc * Bsz * Hd;
    (void)in_sizes; (void)n_in; (void)out_size;

    // ---- prolog: split weights + h into bf16 hi/lo ----
    #define SPLIT(src, dh, dl, nelem) \
        split_pair<<<(int)((nelem) / 1024), 256>>>(src, dh, dl)
    SPLIT(wih0_c0,   wih0h, wih0l, (long)G3H * Hd);
    SPLIT(whh0,      whh0h, whh0l, (long)Cc * G3H * Hd);
    SPLIT(wih,       wihh,  wihl,  (long)(Ll-1) * Cc * G3H * Hd);
    SPLIT(whh,       whhh,  whhl,  (long)(Ll-1) * Cc * G3H * Hd);
    SPLIT(attn_in_w, aiwh,  aiwl,  (long)Ll * G3H * Hd);
    SPLIT(attn_out_w,aowh,  aowl,  (long)Ll * Hd * Hd);
    SPLIT(head_w,    hwh,   hwl,   (long)Oo * Hd);
    SPLIT(h_in,      hh,    hl,    (long)Ll * CBH);
    #undef SPLIT
    gather_x0<<<(Bsz * 32) / 256, 256>>>(tokens, emb);

    dim3 gB(Bsz / 128, G3H / 64, Cc);
    dim3 gD(Bsz / 128, G3H / 64, 2 * Cc);
    dim3 gO(Bsz / 128, Hd  / 64, Cc);

    for (int l = 0; l < Ll; l++) {
        const float* hlp = h_in + (size_t)l * CBH;

        // ---- gi + gh ----
        if (l == 0) {
            dim3 g1(Bsz / 128, G3H / 64, 1);
            gemm_tc<<<g1, 256, SM_TOT>>>(x0h, x0l, wih0h, wih0l, bih0, pgi,
                                         G3H, 0, 0, 0, 0);
            gemm_tc<<<gB, 256, SM_TOT>>>(hh, hl, whh0h, whh0l, bhh0, pgh, G3H,
                                         (long)Bsz * Hd, (long)G3H * Hd, G3H,
                                         (long)Bsz * G3H);
        } else {
            gemm_tc_dual<<<gD, 256, SM_TOT>>>(
                ph, pl,
                wihh + (size_t)(l - 1) * Cc * G3H * Hd,
                wihl + (size_t)(l - 1) * Cc * G3H * Hd,
                bih + (size_t)(l - 1) * Cc * G3H, pgi,
                hh + (size_t)l * CBH, hl + (size_t)l * CBH,
                whhh + (size_t)(l - 1) * Cc * G3H * Hd,
                whhl + (size_t)(l - 1) * Cc * G3H * Hd,
                bhh + (size_t)(l - 1) * Cc * G3H, pgh);
        }

        // ---- GRU (l=0: cells 1..3 read bias directly, no gi buffer) ----
        gru_kernel<<<((long)Cc * Bsz * 32) / 256, 256>>>(
            hlp, (l == 0) ? bih0 : nullptr);

        // ---- QKV ----
        gemm_tc<<<gB, 256, SM_TOT>>>(nh, nl,
                                     aiwh + (size_t)l * G3H * Hd,
                                     aiwl + (size_t)l * G3H * Hd,
                                     attn_in_b + (size_t)l * G3H,
                                     pqkv, G3H,
                                     (long)Bsz * Hd, 0, 0, (long)Bsz * G3H);

        // ---- attention ----
        attn_kernel<<<(Bsz * NHh) / 4, 128>>>();

        // ---- out projection ----
        gemm_tc<<<gO, 256, SM_TOT>>>(aah, aal,
                                     aowh + (size_t)l * Hd * Hd,
                                     aowl + (size_t)l * Hd * Hd,
                                     attn_out_b + (size_t)l * Hd,
                                     pmsg, Hd,
                                     (long)Bsz * Hd, 0, 0, (long)Bsz * Hd);

        // ---- fused LN + gate + blend -> hOut + g_ph/g_pl split ----
        lngate_kernel<<<(Cc * Bsz) / 4, 128>>>(ln_g + (size_t)l * Hd, ln_b + (size_t)l * Hd,
                                               gate_w + (size_t)l * 2 * Hd, gate_b + l,
                                               hOut + (size_t)l * CBH);
    }

    // ---- head: y = h_n[L-1, 0] @ head_w.T + head_b ----
    dim3 gH(Bsz / 128, Oo / 64, 1);
    gemm_tc<<<gH, 256, SM_TOT>>>(ph, pl, hwh, hwl, head_b, yOut, Oo, 0, 0, 0, 0);
}